// round 1
// baseline (speedup 1.0000x reference)
#include <cuda_runtime.h>

// Problem constants
#define VOCAB   100000
#define DDIM    128
#define KDIM    256      // 2*D
#define BATCH   256
#define SEQ     2048

// GEMM tiling
#define BM 128
#define BN 128
#define BK 32
#define NTHREADS 256

// Scratch: ping-pong buffers (level-1 output is 262144*128 floats = 134MB)
__device__ float g_bufA[262144 * 128];
__device__ float g_bufB[262144 * 128];
__device__ float g_Wt[KDIM * DDIM];   // W transposed: Wt[k][n] = W[n][k]

// ---------------------------------------------------------------------------
// packed f32x2 helpers (Blackwell FFMA2 path: 2x fp32 FMA per issue slot)
// ---------------------------------------------------------------------------
__device__ __forceinline__ unsigned long long pack2(float lo, float hi) {
    unsigned long long r;
    asm("mov.b64 %0, {%1, %2};" : "=l"(r) : "f"(lo), "f"(hi));
    return r;
}
__device__ __forceinline__ void unpack2(unsigned long long v, float& lo, float& hi) {
    asm("mov.b64 {%0, %1}, %2;" : "=f"(lo), "=f"(hi) : "l"(v));
}
__device__ __forceinline__ void ffma2(unsigned long long& d,
                                      unsigned long long a,
                                      unsigned long long b) {
    asm("fma.rn.f32x2 %0, %1, %2, %0;" : "+l"(d) : "l"(a), "l"(b));
}

// ---------------------------------------------------------------------------
// W transpose: (128 x 256) row-major -> Wt (256 x 128) row-major
// ---------------------------------------------------------------------------
__global__ void transpose_W_kernel(const float* __restrict__ W) {
    int i = blockIdx.x * blockDim.x + threadIdx.x;
    if (i < DDIM * KDIM) {
        int o = i >> 8;        // / 256
        int d = i & 255;       // % 256
        g_Wt[d * DDIM + o] = W[i];
    }
}

// ---------------------------------------------------------------------------
// Level GEMM: C[M x 128] = A[M x 256] @ Wt + bias
// GATHER=true: A row m is [emb[ids[2m]] ; emb[ids[2m+1]]]
// ---------------------------------------------------------------------------
template <bool GATHER>
__global__ __launch_bounds__(NTHREADS)
void level_gemm(const float* __restrict__ A,
                const int* __restrict__ ids,
                const float* __restrict__ emb,
                const float* __restrict__ bias,
                float* __restrict__ C,
                int M)
{
    __shared__ float As[BK][BM + 4];   // transposed A tile, padded
    __shared__ float Bs[BK][BN];
    __shared__ int   sIds[2 * BM];

    const int tid = threadIdx.x;
    const int block_row = blockIdx.x * BM;

    if (GATHER) {
        // 256 ids for this tile (2 leaves per row)
        sIds[tid] = ids[2 * block_row + tid];
        __syncthreads();
    }

    const int ty = tid >> 4;   // 0..15 (row group)
    const int tx = tid & 15;   // 0..15 (col group)

    // 8x8 fp32 accumulators stored as 8x4 packed f32x2 (pairs along columns)
    unsigned long long acc2[8][4];
#pragma unroll
    for (int i = 0; i < 8; i++)
#pragma unroll
        for (int j = 0; j < 4; j++) acc2[i][j] = 0ULL;

    for (int kc = 0; kc < KDIM; kc += BK) {
        // ---- load A tile (128 x 32), store transposed into As ----
#pragma unroll
        for (int jld = 0; jld < 4; jld++) {
            int f = tid + NTHREADS * jld;       // 0..1023 float4 index
            int r = f >> 3;                     // 0..127 tile row
            int c = (f & 7) << 2;               // 0,4,...,28 col in chunk
            float4 v;
            if (GATHER) {
                int k    = kc + c;
                int side = k >> 7;              // 0: left leaf, 1: right leaf
                int id   = sIds[2 * r + side];
                v = *(const float4*)(emb + (size_t)id * DDIM + (k & 127));
            } else {
                v = *(const float4*)(A + (size_t)(block_row + r) * KDIM + kc + c);
            }
            As[c + 0][r] = v.x;
            As[c + 1][r] = v.y;
            As[c + 2][r] = v.z;
            As[c + 3][r] = v.w;
        }
        // ---- load B tile (32 x 128) from pre-transposed Wt ----
#pragma unroll
        for (int jld = 0; jld < 4; jld++) {
            int f  = tid + NTHREADS * jld;      // float4 index
            int kr = f >> 5;                    // 0..31
            int c  = (f & 31) << 2;             // 0..124
            *(float4*)&Bs[kr][c] = *(const float4*)(g_Wt + (size_t)(kc + kr) * DDIM + c);
        }
        __syncthreads();

        // ---- compute: 32 k-steps, 8x8 microtile via packed FFMA2 ----
#pragma unroll
        for (int kk = 0; kk < BK; kk++) {
            float4 av0 = *(const float4*)&As[kk][ty * 8];
            float4 av1 = *(const float4*)&As[kk][ty * 8 + 4];
            float a[8] = {av0.x, av0.y, av0.z, av0.w, av1.x, av1.y, av1.z, av1.w};

            ulonglong2 bv0 = *(const ulonglong2*)&Bs[kk][tx * 8];
            ulonglong2 bv1 = *(const ulonglong2*)&Bs[kk][tx * 8 + 4];
            unsigned long long b2[4] = {bv0.x, bv0.y, bv1.x, bv1.y};

#pragma unroll
            for (int i = 0; i < 8; i++) {
                unsigned long long a2 = pack2(a[i], a[i]);
#pragma unroll
                for (int jh = 0; jh < 4; jh++) ffma2(acc2[i][jh], a2, b2[jh]);
            }
        }
        __syncthreads();
    }

    // ---- epilogue: unpack, add bias, store ----
    float bias_r[8];
#pragma unroll
    for (int j = 0; j < 8; j++) bias_r[j] = bias[tx * 8 + j];

#pragma unroll
    for (int i = 0; i < 8; i++) {
        float row[8];
#pragma unroll
        for (int jh = 0; jh < 4; jh++) unpack2(acc2[i][jh], row[2 * jh], row[2 * jh + 1]);
#pragma unroll
        for (int j = 0; j < 8; j++) row[j] += bias_r[j];

        size_t r = (size_t)(block_row + ty * 8 + i);
        *(float4*)&C[r * DDIM + tx * 8]     = make_float4(row[0], row[1], row[2], row[3]);
        *(float4*)&C[r * DDIM + tx * 8 + 4] = make_float4(row[4], row[5], row[6], row[7]);
    }
}

// ---------------------------------------------------------------------------
// Host launcher: 1 transpose + 11 level GEMMs (all graph-capturable)
// ---------------------------------------------------------------------------
extern "C" void kernel_launch(void* const* d_in, const int* in_sizes, int n_in,
                              void* d_out, int out_size)
{
    (void)in_sizes; (void)n_in; (void)out_size;
    const int*   ids  = (const int*)d_in[0];     // word_ids (B, L) int32
    const float* emb  = (const float*)d_in[1];   // embedding (VOCAB, 128)
    const float* W    = (const float*)d_in[2];   // W (128, 256)
    const float* bias = (const float*)d_in[3];   // b (128,)
    float* out = (float*)d_out;                  // (256, 128)

    float *bufA = nullptr, *bufB = nullptr;
    cudaGetSymbolAddress((void**)&bufA, g_bufA);
    cudaGetSymbolAddress((void**)&bufB, g_bufB);

    transpose_W_kernel<<<(DDIM * KDIM + 255) / 256, 256>>>(W);

    // Level 1: gathered GEMM, M = B*L/2 = 262144
    int M1 = (BATCH * SEQ) / 2;
    level_gemm<true><<<M1 / BM, NTHREADS>>>(nullptr, ids, emb, bias, bufA, M1);

    // Levels 2..11: plain GEMMs on reinterpreted (nodes/2, 256) views
    float* cur = bufA;
    float* nxt = bufB;
    int nodes = M1;                    // node count currently in `cur`
    while (nodes > BATCH) {
        int Mo = nodes / 2;
        float* dst = (Mo == BATCH) ? out : nxt;
        level_gemm<false><<<Mo / BM, NTHREADS>>>(cur, nullptr, nullptr, bias, dst, Mo);
        float* t = cur; cur = nxt; nxt = t;
        nodes = Mo;
    }
}

// round 3
// speedup vs baseline: 1.9523x; 1.9523x over previous
#include <cuda_runtime.h>
#include <cstdint>

#define VOCAB    100000
#define DDIM     128
#define KDIM     256
#define BATCH    256
#define SEQ      2048

#define NTHREADS 256
#define TILE_M   128

// tcgen05 is an arch-accelerated feature: only emit it in the sm_103a pass.
// The compute_103 (JIT-fallback) pass gets an empty kernel body — never run.
#if !defined(__CUDA_ARCH__) || defined(__CUDA_ARCH_FEAT_SM103_ALL) || \
    (defined(__CUDA_ARCH_SPECIFIC__) && (__CUDA_ARCH_SPECIFIC__ == 1030))
#define HAS_TCGEN05 1
#else
#define HAS_TCGEN05 0
#endif

// ---- SMEM layout (offsets from 1KB-aligned base) ----
#define SM_BHI   0                      // 4 chunks x 16KB  (B hi, bf16, SW128)
#define SM_BLO   65536                  // 4 chunks x 16KB  (B lo)
#define SM_A     131072                 // 2 bufs x (hi 16KB + lo 16KB)
#define SM_HDR   196608
#define SM_TMEMP (SM_HDR + 0)
#define SM_MBAR0 (SM_HDR + 8)
#define SM_MBAR1 (SM_HDR + 16)
#define SM_IDS   (SM_HDR + 32)          // 256 ints
#define SM_BIAS  (SM_HDR + 32 + 1024)   // 128 floats
#define DYN_SMEM 200704

// idesc kind::f16, bf16 x bf16 -> f32, M=128, N=128
#define MMA_IDESC 0x8200490u

// fp32 ping-pong intermediates (level outputs)
__device__ float g_bufA[262144 * 128];
__device__ float g_bufB[262144 * 128];

// ---------------- PTX helpers ----------------
__device__ __forceinline__ uint32_t smem_u32(const void* p) {
    uint32_t a;
    asm("{ .reg .u64 t; cvta.to.shared.u64 t, %1; cvt.u32.u64 %0, t; }" : "=r"(a) : "l"(p));
    return a;
}
__device__ __forceinline__ bool elect_one() {
    uint32_t pred;
    asm volatile("{ .reg .pred p; elect.sync _|p, 0xFFFFFFFF; selp.b32 %0, 1, 0, p; }" : "=r"(pred));
    return pred != 0;
}
__device__ __forceinline__ void sts128(uint32_t addr, uint32_t a, uint32_t b, uint32_t c, uint32_t d) {
    asm volatile("st.shared.v4.b32 [%0], {%1,%2,%3,%4};" :: "r"(addr), "r"(a), "r"(b), "r"(c), "r"(d) : "memory");
}
__device__ __forceinline__ int lds_s32(uint32_t addr) {
    int v; asm volatile("ld.shared.b32 %0, [%1];" : "=r"(v) : "r"(addr)); return v;
}
__device__ __forceinline__ float lds_f32(uint32_t addr) {
    float v; asm volatile("ld.shared.f32 %0, [%1];" : "=f"(v) : "r"(addr)); return v;
}
__device__ __forceinline__ void sts_b32(uint32_t addr, uint32_t v) {
    asm volatile("st.shared.b32 [%0], %1;" :: "r"(addr), "r"(v) : "memory");
}
__device__ __forceinline__ void mbar_init(uint32_t addr, uint32_t count) {
    asm volatile("mbarrier.init.shared.b64 [%0], %1;" :: "r"(addr), "r"(count) : "memory");
}
__device__ __forceinline__ void fence_proxy_async_s() {
    asm volatile("fence.proxy.async.shared::cta;" ::: "memory");
}

#if HAS_TCGEN05
__device__ __forceinline__ void mbar_wait(uint32_t addr, uint32_t parity) {
    asm volatile(
        "{\n\t.reg .pred P;\n\t"
        "W%=:\n\t"
        "mbarrier.try_wait.parity.acquire.cta.shared::cta.b64 P, [%0], %1, 0x989680;\n\t"
        "@P bra.uni D%=;\n\t"
        "bra.uni W%=;\n\t"
        "D%=:\n\t}"
        :: "r"(addr), "r"(parity) : "memory");
}
__device__ __forceinline__ void tmem_alloc(uint32_t dst_smem, uint32_t ncols) {
    asm volatile("tcgen05.alloc.cta_group::1.sync.aligned.shared::cta.b32 [%0], %1;"
                 :: "r"(dst_smem), "r"(ncols) : "memory");
}
__device__ __forceinline__ void tmem_relinquish() {
    asm volatile("tcgen05.relinquish_alloc_permit.cta_group::1.sync.aligned;");
}
__device__ __forceinline__ void tmem_dealloc(uint32_t tmem, uint32_t ncols) {
    asm volatile("tcgen05.dealloc.cta_group::1.sync.aligned.b32 %0, %1;" :: "r"(tmem), "r"(ncols));
}
__device__ __forceinline__ void mma_f16_ss(uint32_t d, uint64_t ad, uint64_t bd, uint32_t en) {
    asm volatile(
        "{\n\t.reg .pred p;\n\tsetp.ne.u32 p, %4, 0;\n\t"
        "tcgen05.mma.cta_group::1.kind::f16 [%0], %1, %2, %3, {%5,%5,%5,%5}, p;\n\t}"
        :: "r"(d), "l"(ad), "l"(bd), "r"(MMA_IDESC), "r"(en), "r"(0u) : "memory");
}
__device__ __forceinline__ void mma_commit(uint32_t mbar) {
    asm volatile("tcgen05.commit.cta_group::1.mbarrier::arrive::one.shared::cluster.b64 [%0];"
                 :: "r"(mbar) : "memory");
}
__device__ __forceinline__ void fence_after() {
    asm volatile("tcgen05.fence::after_thread_sync;" ::: "memory");
}
__device__ __forceinline__ void fence_before() {
    asm volatile("tcgen05.fence::before_thread_sync;" ::: "memory");
}
__device__ __forceinline__ void wait_ld() {
    asm volatile("tcgen05.wait::ld.sync.aligned;" ::: "memory");
}
__device__ __forceinline__ void ldtm32(uint32_t* r, uint32_t tmem_addr) {
    asm volatile(
        "tcgen05.ld.sync.aligned.32x32b.x32.b32 "
        "{%0, %1, %2, %3, %4, %5, %6, %7, "
        " %8, %9, %10, %11, %12, %13, %14, %15, "
        " %16, %17, %18, %19, %20, %21, %22, %23, "
        " %24, %25, %26, %27, %28, %29, %30, %31}, [%32];"
        : "=r"(r[0]), "=r"(r[1]), "=r"(r[2]), "=r"(r[3]),
          "=r"(r[4]), "=r"(r[5]), "=r"(r[6]), "=r"(r[7]),
          "=r"(r[8]), "=r"(r[9]), "=r"(r[10]), "=r"(r[11]),
          "=r"(r[12]), "=r"(r[13]), "=r"(r[14]), "=r"(r[15]),
          "=r"(r[16]), "=r"(r[17]), "=r"(r[18]), "=r"(r[19]),
          "=r"(r[20]), "=r"(r[21]), "=r"(r[22]), "=r"(r[23]),
          "=r"(r[24]), "=r"(r[25]), "=r"(r[26]), "=r"(r[27]),
          "=r"(r[28]), "=r"(r[29]), "=r"(r[30]), "=r"(r[31])
        : "r"(tmem_addr));
}
#endif // HAS_TCGEN05

// SW128 swizzle (byte offsets, tile base must be 1024B-aligned)
__device__ __forceinline__ uint32_t swz(uint32_t off) { return off ^ ((off >> 3) & 0x70); }

// SMEM descriptor: SW128, version=1 (Blackwell), SBO=64, LBO=1
__device__ __forceinline__ uint64_t mk_desc(uint32_t addr) {
    const uint64_t base = (uint64_t(2) << 61) | (uint64_t(1) << 46) |
                          (uint64_t(64) << 32) | (uint64_t(1) << 16);
    return base | ((uint64_t)(addr >> 4) & 0x3FFF);
}

// split 8 fp32 -> 8 bf16 hi (uint4) + 8 bf16 lo (uint4); element i in low half
__device__ __forceinline__ void split8(const float4& v0, const float4& v1, uint4& h, uint4& l) {
    float f[8] = {v0.x, v0.y, v0.z, v0.w, v1.x, v1.y, v1.z, v1.w};
    uint32_t hh[4], ll[4];
#pragma unroll
    for (int q = 0; q < 4; q++) {
        float a = f[2 * q], b = f[2 * q + 1];
        uint32_t hv;
        asm("cvt.rn.bf16x2.f32 %0, %1, %2;" : "=r"(hv) : "f"(b), "f"(a));  // low half = a
        hh[q] = hv;
        float ha = __uint_as_float(hv << 16);
        float hb = __uint_as_float(hv & 0xFFFF0000u);
        float la = a - ha, lb = b - hb;  // exact residual
        asm("cvt.rn.bf16x2.f32 %0, %1, %2;" : "=r"(ll[q]) : "f"(lb), "f"(la));
    }
    h = make_uint4(hh[0], hh[1], hh[2], hh[3]);
    l = make_uint4(ll[0], ll[1], ll[2], ll[3]);
}

// ---------------------------------------------------------------------------
// Persistent level GEMM: C[M x 128] = A[M x 256] @ W^T + bias  (3x bf16 split)
// GATHER: A row m = [emb[ids[2m]] ; emb[ids[2m+1]]]
// ---------------------------------------------------------------------------
template <bool GATHER>
__global__ __launch_bounds__(NTHREADS, 1)
void level_tc(const float* __restrict__ A, const int* __restrict__ ids,
              const float* __restrict__ emb, const float* __restrict__ W,
              const float* __restrict__ bias, float* __restrict__ C, int numTiles)
{
#if HAS_TCGEN05
    extern __shared__ char dsm[];
    const uint32_t sb = (smem_u32(dsm) + 1023) & ~1023u;

    const int tid = threadIdx.x;
    const int wid = tid >> 5;
    const int lid = tid & 31;

    // ---- one-time: mbarriers, bias, B split into SMEM, TMEM alloc ----
    if (tid == 0) { mbar_init(sb + SM_MBAR0, 1); mbar_init(sb + SM_MBAR1, 1); }
    if (tid < 128) sts_b32(sb + SM_BIAS + tid * 4, __float_as_uint(bias[tid]));

    {
        const int r = tid >> 1, half = tid & 1;
#pragma unroll
        for (int g = 0; g < 16; g++) {
            int col0 = half * 128 + g * 8;                     // fp32 col in W row
            float4 v0 = *(const float4*)(W + r * KDIM + col0);
            float4 v1 = *(const float4*)(W + r * KDIM + col0 + 4);
            uint4 h, l; split8(v0, v1, h, l);
            int chunk = col0 >> 6, lc = col0 & 63;
            uint32_t off = chunk * 16384 + swz(r * 128 + lc * 2);
            sts128(sb + SM_BHI + off, h.x, h.y, h.z, h.w);
            sts128(sb + SM_BLO + off, l.x, l.y, l.z, l.w);
        }
    }
    fence_proxy_async_s();
    __syncthreads();

    if (wid == 0) { tmem_alloc(sb + SM_TMEMP, 128); tmem_relinquish(); }
    __syncthreads();
    const uint32_t tmem = (uint32_t)lds_s32(sb + SM_TMEMP);

    int loads0 = 0, loads1 = 0;   // per-buffer load counters (== commit counters)

    const int r = tid >> 1, half = tid & 1;

    for (int tile = blockIdx.x; tile < numTiles; tile += gridDim.x) {
        const int tileRow = tile * TILE_M;

        if (GATHER) {
            sts_b32(sb + SM_IDS + tid * 4, (uint32_t)ids[2 * tileRow + tid]);
            __syncthreads();
        }

        // ---- load A chunk c into buffer b (split fp32 -> bf16 hi/lo) ----
        auto load_chunk = [&](int c, int b) {
            const float* src;
            if (GATHER) {
                int id = lds_s32(sb + SM_IDS + (2 * r + (c >> 1)) * 4);
                src = emb + (size_t)id * DDIM + (c & 1) * 64;
            } else {
                src = A + (size_t)(tileRow + r) * KDIM + c * 64;
            }
            uint32_t hiB = sb + SM_A + b * 32768;
            uint32_t loB = hiB + 16384;
#pragma unroll
            for (int g = 0; g < 4; g++) {
                int col0 = half * 32 + g * 8;
                float4 v0 = *(const float4*)(src + col0);
                float4 v1 = *(const float4*)(src + col0 + 4);
                uint4 h, l; split8(v0, v1, h, l);
                uint32_t off = swz(r * 128 + col0 * 2);
                sts128(hiB + off, h.x, h.y, h.z, h.w);
                sts128(loB + off, l.x, l.y, l.z, l.w);
            }
            fence_proxy_async_s();
        };

        // chunk 0 -> buf 0
        if (loads0 > 0) mbar_wait(sb + SM_MBAR0, (loads0 - 1) & 1);
        loads0++;
        load_chunk(0, 0);
        __syncthreads();

#pragma unroll
        for (int c = 0; c < 4; c++) {
            const int b = c & 1;
            if (wid == 0 && elect_one()) {
                uint32_t aHi = sb + SM_A + b * 32768;
                uint64_t adh = mk_desc(aHi);
                uint64_t adl = mk_desc(aHi + 16384);
                uint64_t bdh = mk_desc(sb + SM_BHI + c * 16384);
                uint64_t bdl = mk_desc(sb + SM_BLO + c * 16384);
#pragma unroll
                for (int ks = 0; ks < 4; ks++)
                    mma_f16_ss(tmem, adh + 2 * ks, bdh + 2 * ks, (c > 0 || ks > 0) ? 1u : 0u);
#pragma unroll
                for (int ks = 0; ks < 4; ks++)
                    mma_f16_ss(tmem, adh + 2 * ks, bdl + 2 * ks, 1u);
#pragma unroll
                for (int ks = 0; ks < 4; ks++)
                    mma_f16_ss(tmem, adl + 2 * ks, bdh + 2 * ks, 1u);
                mma_commit(sb + (b ? SM_MBAR1 : SM_MBAR0));
            }
            if (c < 3) {
                const int nb = b ^ 1;
                if (nb == 0) {
                    if (loads0 > 0) mbar_wait(sb + SM_MBAR0, (loads0 - 1) & 1);
                    loads0++;
                } else {
                    if (loads1 > 0) mbar_wait(sb + SM_MBAR1, (loads1 - 1) & 1);
                    loads1++;
                }
                load_chunk(c + 1, nb);
                __syncthreads();
            }
        }

        // ---- epilogue: wait last commit (buf1), read D, add bias, store ----
        mbar_wait(sb + SM_MBAR1, 1);   // 2 commits/tile on buf1 -> last is always parity 1
        fence_after();

        const int colbase = (wid >> 2) * 64;
        uint32_t d0[32], d1[32];
        ldtm32(d0, tmem + colbase);
        ldtm32(d1, tmem + colbase + 32);
        wait_ld();

        const int rowg = tileRow + (wid & 3) * 32 + lid;
        float* outp = C + (size_t)rowg * DDIM + colbase;
#pragma unroll
        for (int q = 0; q < 8; q++) {
            float4 o;
            o.x = __uint_as_float(d0[4 * q + 0]) + lds_f32(sb + SM_BIAS + (colbase + 4 * q + 0) * 4);
            o.y = __uint_as_float(d0[4 * q + 1]) + lds_f32(sb + SM_BIAS + (colbase + 4 * q + 1) * 4);
            o.z = __uint_as_float(d0[4 * q + 2]) + lds_f32(sb + SM_BIAS + (colbase + 4 * q + 2) * 4);
            o.w = __uint_as_float(d0[4 * q + 3]) + lds_f32(sb + SM_BIAS + (colbase + 4 * q + 3) * 4);
            *(float4*)(outp + 4 * q) = o;
        }
#pragma unroll
        for (int q = 0; q < 8; q++) {
            float4 o;
            o.x = __uint_as_float(d1[4 * q + 0]) + lds_f32(sb + SM_BIAS + (colbase + 32 + 4 * q + 0) * 4);
            o.y = __uint_as_float(d1[4 * q + 1]) + lds_f32(sb + SM_BIAS + (colbase + 32 + 4 * q + 1) * 4);
            o.z = __uint_as_float(d1[4 * q + 2]) + lds_f32(sb + SM_BIAS + (colbase + 32 + 4 * q + 2) * 4);
            o.w = __uint_as_float(d1[4 * q + 3]) + lds_f32(sb + SM_BIAS + (colbase + 32 + 4 * q + 3) * 4);
            *(float4*)(outp + 32 + 4 * q) = o;
        }
        fence_before();
        __syncthreads();   // LDTM done in all warps before next tile's first MMA overwrites D
    }

    __syncthreads();
    if (wid == 0) tmem_dealloc(tmem, 128);
#else
    // Fallback pass (compute_103 PTX for JIT) — never executed on GB300;
    // the sm_103a cubin is always present and preferred.
    (void)A; (void)ids; (void)emb; (void)W; (void)bias; (void)C; (void)numTiles;
#endif
}

// ---------------------------------------------------------------------------
// Host launcher
// ---------------------------------------------------------------------------
extern "C" void kernel_launch(void* const* d_in, const int* in_sizes, int n_in,
                              void* d_out, int out_size)
{
    (void)in_sizes; (void)n_in; (void)out_size;
    const int*   ids  = (const int*)d_in[0];
    const float* emb  = (const float*)d_in[1];
    const float* W    = (const float*)d_in[2];
    const float* bias = (const float*)d_in[3];
    float* out = (float*)d_out;

    static bool attr_set = false;
    if (!attr_set) {
        cudaFuncSetAttribute(level_tc<true>,  cudaFuncAttributeMaxDynamicSharedMemorySize, DYN_SMEM);
        cudaFuncSetAttribute(level_tc<false>, cudaFuncAttributeMaxDynamicSharedMemorySize, DYN_SMEM);
        attr_set = true;
    }

    float *bufA = nullptr, *bufB = nullptr;
    cudaGetSymbolAddress((void**)&bufA, g_bufA);
    cudaGetSymbolAddress((void**)&bufB, g_bufB);

    // Level 1: gathered, M = B*L/2
    int M = (BATCH * SEQ) / 2;
    {
        int tiles = M / TILE_M;
        int grid = tiles < 148 ? tiles : 148;
        level_tc<true><<<grid, NTHREADS, DYN_SMEM>>>(nullptr, ids, emb, W, bias, bufA, tiles);
    }

    float* cur = bufA;
    float* nxt = bufB;
    int nodes = M;
    while (nodes > BATCH) {
        int Mo = nodes / 2;
        int tiles = Mo / TILE_M;
        int grid = tiles < 148 ? tiles : 148;
        float* dst = (Mo == BATCH) ? out : nxt;
        level_tc<false><<<grid, NTHREADS, DYN_SMEM>>>(cur, nullptr, nullptr, W, bias, dst, tiles);
        float* t = cur; cur = nxt; nxt = t;
        nodes = Mo;
    }
}

// round 4
// speedup vs baseline: 2.1039x; 1.0777x over previous
#include <cuda_runtime.h>
#include <cstdint>

#define VOCAB    100000
#define VOCABPAD 100096                 // 782 tiles of 128
#define DDIM     128
#define KDIM     256
#define BATCH    256
#define SEQ      2048

#define NTHREADS 256
#define TILE_M   128

// tcgen05 is arch-accelerated: only emit in the sm_103a pass; the compute_103
// JIT-fallback pass gets empty bodies (never executed on GB300).
#if !defined(__CUDA_ARCH__) || defined(__CUDA_ARCH_FEAT_SM103_ALL) || \
    (defined(__CUDA_ARCH_SPECIFIC__) && (__CUDA_ARCH_SPECIFIC__ == 1030))
#define HAS_TCGEN05 1
#else
#define HAS_TCGEN05 0
#endif

// ---- shared SMEM frame (both kernels), offsets from 1KB-aligned base ----
#define SM_BHI   0                      // level: 4x16KB chunks | pre: 2x32KB
#define SM_BLO   65536
#define SM_A     131072                 // 2 bufs x (hi 16KB + lo 16KB)
#define SM_HDR   196608
#define SM_TMEMP (SM_HDR + 0)
#define SM_MBAR0 (SM_HDR + 8)
#define SM_MBAR1 (SM_HDR + 16)
#define SM_IDS   (SM_HDR + 32)          // 512 ints (gather2)
#define SM_BIAS  (SM_HDR + 32 + 2048)   // 128 floats
#define DYN_SMEM 200704

#define IDESC_N128 0x8200490u           // f16-kind, bf16->f32, M=128, N=128
#define IDESC_N256 0x8400490u           // f16-kind, bf16->f32, M=128, N=256

// scratch
__device__ float g_bufA[131072 * 128];
__device__ float g_bufB[65536 * 128];
__device__ float g_EL[VOCABPAD * 128];
__device__ float g_ER[VOCABPAD * 128];

// ---------------- PTX helpers ----------------
__device__ __forceinline__ uint32_t smem_u32(const void* p) {
    uint32_t a;
    asm("{ .reg .u64 t; cvta.to.shared.u64 t, %1; cvt.u32.u64 %0, t; }" : "=r"(a) : "l"(p));
    return a;
}
__device__ __forceinline__ bool elect_one() {
    uint32_t pred;
    asm volatile("{ .reg .pred p; elect.sync _|p, 0xFFFFFFFF; selp.b32 %0, 1, 0, p; }" : "=r"(pred));
    return pred != 0;
}
__device__ __forceinline__ void sts128(uint32_t a, uint32_t x, uint32_t y, uint32_t z, uint32_t w) {
    asm volatile("st.shared.v4.b32 [%0], {%1,%2,%3,%4};" :: "r"(a), "r"(x), "r"(y), "r"(z), "r"(w) : "memory");
}
__device__ __forceinline__ int lds_s32(uint32_t a) {
    int v; asm volatile("ld.shared.b32 %0, [%1];" : "=r"(v) : "r"(a)); return v;
}
__device__ __forceinline__ float lds_f32(uint32_t a) {
    float v; asm volatile("ld.shared.f32 %0, [%1];" : "=f"(v) : "r"(a)); return v;
}
__device__ __forceinline__ void sts_b32(uint32_t a, uint32_t v) {
    asm volatile("st.shared.b32 [%0], %1;" :: "r"(a), "r"(v) : "memory");
}
__device__ __forceinline__ void mbar_init(uint32_t a, uint32_t c) {
    asm volatile("mbarrier.init.shared.b64 [%0], %1;" :: "r"(a), "r"(c) : "memory");
}
__device__ __forceinline__ void fence_proxy_async_s() {
    asm volatile("fence.proxy.async.shared::cta;" ::: "memory");
}

#if HAS_TCGEN05
__device__ __forceinline__ void mbar_wait(uint32_t a, uint32_t parity) {
    asm volatile(
        "{\n\t.reg .pred P;\n\t"
        "W%=:\n\t"
        "mbarrier.try_wait.parity.acquire.cta.shared::cta.b64 P, [%0], %1, 0x989680;\n\t"
        "@P bra.uni D%=;\n\t"
        "bra.uni W%=;\n\t"
        "D%=:\n\t}"
        :: "r"(a), "r"(parity) : "memory");
}
__device__ __forceinline__ void tmem_alloc(uint32_t dst, uint32_t n) {
    asm volatile("tcgen05.alloc.cta_group::1.sync.aligned.shared::cta.b32 [%0], %1;"
                 :: "r"(dst), "r"(n) : "memory");
}
__device__ __forceinline__ void tmem_relinquish() {
    asm volatile("tcgen05.relinquish_alloc_permit.cta_group::1.sync.aligned;");
}
__device__ __forceinline__ void tmem_dealloc(uint32_t t, uint32_t n) {
    asm volatile("tcgen05.dealloc.cta_group::1.sync.aligned.b32 %0, %1;" :: "r"(t), "r"(n));
}
__device__ __forceinline__ void mma_f16_ss(uint32_t d, uint64_t ad, uint64_t bd, uint32_t idesc, uint32_t en) {
    asm volatile(
        "{\n\t.reg .pred p;\n\tsetp.ne.u32 p, %4, 0;\n\t"
        "tcgen05.mma.cta_group::1.kind::f16 [%0], %1, %2, %3, {%5,%5,%5,%5}, p;\n\t}"
        :: "r"(d), "l"(ad), "l"(bd), "r"(idesc), "r"(en), "r"(0u) : "memory");
}
__device__ __forceinline__ void mma_commit(uint32_t mbar) {
    asm volatile("tcgen05.commit.cta_group::1.mbarrier::arrive::one.shared::cluster.b64 [%0];"
                 :: "r"(mbar) : "memory");
}
__device__ __forceinline__ void fence_after()  { asm volatile("tcgen05.fence::after_thread_sync;"  ::: "memory"); }
__device__ __forceinline__ void fence_before() { asm volatile("tcgen05.fence::before_thread_sync;" ::: "memory"); }
__device__ __forceinline__ void wait_ld()      { asm volatile("tcgen05.wait::ld.sync.aligned;"     ::: "memory"); }
__device__ __forceinline__ void ldtm32(uint32_t* r, uint32_t ta) {
    asm volatile(
        "tcgen05.ld.sync.aligned.32x32b.x32.b32 "
        "{%0, %1, %2, %3, %4, %5, %6, %7, "
        " %8, %9, %10, %11, %12, %13, %14, %15, "
        " %16, %17, %18, %19, %20, %21, %22, %23, "
        " %24, %25, %26, %27, %28, %29, %30, %31}, [%32];"
        : "=r"(r[0]), "=r"(r[1]), "=r"(r[2]), "=r"(r[3]),
          "=r"(r[4]), "=r"(r[5]), "=r"(r[6]), "=r"(r[7]),
          "=r"(r[8]), "=r"(r[9]), "=r"(r[10]), "=r"(r[11]),
          "=r"(r[12]), "=r"(r[13]), "=r"(r[14]), "=r"(r[15]),
          "=r"(r[16]), "=r"(r[17]), "=r"(r[18]), "=r"(r[19]),
          "=r"(r[20]), "=r"(r[21]), "=r"(r[22]), "=r"(r[23]),
          "=r"(r[24]), "=r"(r[25]), "=r"(r[26]), "=r"(r[27]),
          "=r"(r[28]), "=r"(r[29]), "=r"(r[30]), "=r"(r[31])
        : "r"(ta));
}
#endif // HAS_TCGEN05

__device__ __forceinline__ uint32_t swz(uint32_t off) { return off ^ ((off >> 3) & 0x70); }

__device__ __forceinline__ uint64_t mk_desc(uint32_t addr) {
    const uint64_t base = (uint64_t(2) << 61) | (uint64_t(1) << 46) |
                          (uint64_t(64) << 32) | (uint64_t(1) << 16);
    return base | ((uint64_t)(addr >> 4) & 0x3FFF);
}

// split 8 fp32 -> bf16 hi + exact-residual bf16 lo (element 2q in low half)
__device__ __forceinline__ void split8(const float4& v0, const float4& v1, uint4& h, uint4& l) {
    float f[8] = {v0.x, v0.y, v0.z, v0.w, v1.x, v1.y, v1.z, v1.w};
    uint32_t hh[4], ll[4];
#pragma unroll
    for (int q = 0; q < 4; q++) {
        float a = f[2 * q], b = f[2 * q + 1];
        uint32_t hv;
        asm("cvt.rn.bf16x2.f32 %0, %1, %2;" : "=r"(hv) : "f"(b), "f"(a));
        hh[q] = hv;
        float ha = __uint_as_float(hv << 16);
        float hb = __uint_as_float(hv & 0xFFFF0000u);
        asm("cvt.rn.bf16x2.f32 %0, %1, %2;" : "=r"(ll[q]) : "f"(b - hb), "f"(a - ha));
    }
    h = make_uint4(hh[0], hh[1], hh[2], hh[3]);
    l = make_uint4(ll[0], ll[1], ll[2], ll[3]);
}

// ---------------------------------------------------------------------------
// Kernel 1: precompute  EL = emb @ W[:, :128]^T,  ER = emb @ W[:, 128:]^T
// M tiles over vocab (padded), N=256 (EL|ER fused), K=128 (2 chunks of 64).
// TMEM: D double-buffered at cols 0 and 256.
// ---------------------------------------------------------------------------
__global__ __launch_bounds__(NTHREADS, 1)
void precompute_tc(const float* __restrict__ emb, const float* __restrict__ W,
                   float* __restrict__ EL, float* __restrict__ ER, int numTiles)
{
#if HAS_TCGEN05
    extern __shared__ char dsm[];
    const uint32_t sb = (smem_u32(dsm) + 1023) & ~1023u;
    const int tid = threadIdx.x, wid = tid >> 5, lid = tid & 31;

    if (tid == 0) { mbar_init(sb + SM_MBAR0, 1); mbar_init(sb + SM_MBAR1, 1); }

    // B build: row n (=tid): n<128 -> W[n][k], else W[n-128][128+k]; k in [0,128)
    {
        const int n = tid;
        const float* wrow = W + (size_t)(n & 127) * KDIM + (n >> 7) * 128;
#pragma unroll
        for (int g = 0; g < 16; g++) {
            int k0 = g * 8;
            float4 v0 = *(const float4*)(wrow + k0);
            float4 v1 = *(const float4*)(wrow + k0 + 4);
            uint4 h, l; split8(v0, v1, h, l);
            int chunk = k0 >> 6, lc = k0 & 63;
            uint32_t off = chunk * 32768 + swz(n * 128 + lc * 2);
            sts128(sb + SM_BHI + off, h.x, h.y, h.z, h.w);
            sts128(sb + SM_BLO + off, l.x, l.y, l.z, l.w);
        }
    }
    fence_proxy_async_s();
    __syncthreads();

    if (wid == 0) { tmem_alloc(sb + SM_TMEMP, 512); tmem_relinquish(); }
    __syncthreads();
    const uint32_t tmem = (uint32_t)lds_s32(sb + SM_TMEMP);

    const int r = tid >> 1, half = tid & 1;
    int loads0 = 0, loads1 = 0;
    int p = 0, prevP = 0, prevRow = 0;
    bool havePrev = false;

    for (int tile = blockIdx.x; tile < numTiles; tile += gridDim.x) {
        const int tileRow = tile * TILE_M;

#pragma unroll
        for (int c = 0; c < 2; c++) {
            if (c == 0) { if (loads0 > 0) mbar_wait(sb + SM_MBAR0, (loads0 - 1) & 1); loads0++; }
            else        { if (loads1 > 0) mbar_wait(sb + SM_MBAR1, (loads1 - 1) & 1); loads1++; }

            int er = tileRow + r; if (er > VOCAB - 1) er = VOCAB - 1;
            const float* src = emb + (size_t)er * DDIM + c * 64;
            float4 v[8];
#pragma unroll
            for (int g = 0; g < 4; g++) {
                int col0 = half * 32 + g * 8;
                v[2 * g]     = *(const float4*)(src + col0);
                v[2 * g + 1] = *(const float4*)(src + col0 + 4);
            }

            // deferred epilogue of previous tile (overlaps LDG in flight)
            if (c == 0 && havePrev) {
                mbar_wait(sb + SM_MBAR1, (loads1 - 1) & 1);   // prev tile last commit
                fence_after();
                const int rowg = prevRow + (wid & 3) * 32 + lid;
                float* dstB = ((wid >> 2) == 0 ? EL : ER) + (size_t)rowg * DDIM;
                const uint32_t dbase = tmem + prevP * 256 + (wid >> 2) * 128;
#pragma unroll
                for (int q = 0; q < 4; q++) {
                    uint32_t d[32];
                    ldtm32(d, dbase + q * 32);
                    wait_ld();
#pragma unroll
                    for (int u = 0; u < 8; u++)
                        *(float4*)(dstB + q * 32 + u * 4) =
                            make_float4(__uint_as_float(d[4*u+0]), __uint_as_float(d[4*u+1]),
                                        __uint_as_float(d[4*u+2]), __uint_as_float(d[4*u+3]));
                }
                fence_before();
            }

            uint32_t hiB = sb + SM_A + c * 32768, loB = hiB + 16384;
#pragma unroll
            for (int g = 0; g < 4; g++) {
                int col0 = half * 32 + g * 8;
                uint4 h, l; split8(v[2 * g], v[2 * g + 1], h, l);
                uint32_t off = swz(r * 128 + col0 * 2);
                sts128(hiB + off, h.x, h.y, h.z, h.w);
                sts128(loB + off, l.x, l.y, l.z, l.w);
            }
            fence_proxy_async_s();
            __syncthreads();

            if (wid == 0 && elect_one()) {
                uint32_t aHi = sb + SM_A + c * 32768;
                uint64_t adh = mk_desc(aHi), adl = mk_desc(aHi + 16384);
                uint64_t bdh = mk_desc(sb + SM_BHI + c * 32768);
                uint64_t bdl = mk_desc(sb + SM_BLO + c * 32768);
                uint32_t dA = tmem + p * 256;
#pragma unroll
                for (int ks = 0; ks < 4; ks++)
                    mma_f16_ss(dA, adh + 2 * ks, bdh + 2 * ks, IDESC_N256, (c > 0 || ks > 0) ? 1u : 0u);
#pragma unroll
                for (int ks = 0; ks < 4; ks++)
                    mma_f16_ss(dA, adh + 2 * ks, bdl + 2 * ks, IDESC_N256, 1u);
#pragma unroll
                for (int ks = 0; ks < 4; ks++)
                    mma_f16_ss(dA, adl + 2 * ks, bdh + 2 * ks, IDESC_N256, 1u);
                mma_commit(sb + (c ? SM_MBAR1 : SM_MBAR0));
            }
        }
        prevP = p; prevRow = tileRow; p ^= 1; havePrev = true;
    }

    if (havePrev) {   // final epilogue
        mbar_wait(sb + SM_MBAR1, (loads1 - 1) & 1);
        fence_after();
        const int rowg = prevRow + (wid & 3) * 32 + lid;
        float* dstB = ((wid >> 2) == 0 ? EL : ER) + (size_t)rowg * DDIM;
        const uint32_t dbase = tmem + prevP * 256 + (wid >> 2) * 128;
#pragma unroll
        for (int q = 0; q < 4; q++) {
            uint32_t d[32];
            ldtm32(d, dbase + q * 32);
            wait_ld();
#pragma unroll
            for (int u = 0; u < 8; u++)
                *(float4*)(dstB + q * 32 + u * 4) =
                    make_float4(__uint_as_float(d[4*u+0]), __uint_as_float(d[4*u+1]),
                                __uint_as_float(d[4*u+2]), __uint_as_float(d[4*u+3]));
        }
        fence_before();
    }
    __syncthreads();
    if (wid == 0) tmem_dealloc(tmem, 512);
#else
    (void)emb; (void)W; (void)EL; (void)ER; (void)numTiles;
#endif
}

// ---------------------------------------------------------------------------
// Kernel 2: level GEMM  C[M x 128] = A[M x 256] @ W^T + bias
// MODE 0: A from memory (prev level, reinterpreted).
// MODE 1 (fused level 1+2): A row m = [o(2m); o(2m+1)], o(j)=EL[ids[2j]]+ER[ids[2j+1]]+b
// TMEM: D double-buffered at cols 0 and 128; deferred epilogue.
// ---------------------------------------------------------------------------
template <int MODE>
__global__ __launch_bounds__(NTHREADS, 1)
void level_tc(const float* __restrict__ A, const int* __restrict__ ids,
              const float* __restrict__ EL, const float* __restrict__ ER,
              const float* __restrict__ W, const float* __restrict__ bias,
              float* __restrict__ C, int numTiles)
{
#if HAS_TCGEN05
    extern __shared__ char dsm[];
    const uint32_t sb = (smem_u32(dsm) + 1023) & ~1023u;
    const int tid = threadIdx.x, wid = tid >> 5, lid = tid & 31;

    if (tid == 0) { mbar_init(sb + SM_MBAR0, 1); mbar_init(sb + SM_MBAR1, 1); }
    if (tid < 128) sts_b32(sb + SM_BIAS + tid * 4, __float_as_uint(bias[tid]));

    // B = W (128 x 256), split into 4 K-chunks of 64, SW128
    {
        const int n = tid >> 1, h2 = tid & 1;
#pragma unroll
        for (int g = 0; g < 16; g++) {
            int k0 = h2 * 128 + g * 8;
            float4 v0 = *(const float4*)(W + (size_t)n * KDIM + k0);
            float4 v1 = *(const float4*)(W + (size_t)n * KDIM + k0 + 4);
            uint4 h, l; split8(v0, v1, h, l);
            int chunk = k0 >> 6, lc = k0 & 63;
            uint32_t off = chunk * 16384 + swz(n * 128 + lc * 2);
            sts128(sb + SM_BHI + off, h.x, h.y, h.z, h.w);
            sts128(sb + SM_BLO + off, l.x, l.y, l.z, l.w);
        }
    }
    fence_proxy_async_s();
    __syncthreads();

    if (wid == 0) { tmem_alloc(sb + SM_TMEMP, 256); tmem_relinquish(); }
    __syncthreads();
    const uint32_t tmem = (uint32_t)lds_s32(sb + SM_TMEMP);

    const int r = tid >> 1, half = tid & 1;
    int loads0 = 0, loads1 = 0;
    int p = 0, prevP = 0, prevRow = 0;
    bool havePrev = false;

    for (int tile = blockIdx.x; tile < numTiles; tile += gridDim.x) {
        const int tileRow = tile * TILE_M;

        if (MODE == 1) {
            sts_b32(sb + SM_IDS + tid * 4,       (uint32_t)ids[4 * tileRow + tid]);
            sts_b32(sb + SM_IDS + (tid+256) * 4, (uint32_t)ids[4 * tileRow + tid + 256]);
            __syncthreads();
        }

#pragma unroll
        for (int c = 0; c < 4; c++) {
            const int b = c & 1;
            if (b == 0) { if (loads0 > 0) mbar_wait(sb + SM_MBAR0, (loads0 - 1) & 1); loads0++; }
            else        { if (loads1 > 0) mbar_wait(sb + SM_MBAR1, (loads1 - 1) & 1); loads1++; }

            float4 v[8];
            if (MODE == 1) {
                const int jj = 2 * r + (c >> 1);
                const int id0 = lds_s32(sb + SM_IDS + (2 * jj) * 4);
                const int id1 = lds_s32(sb + SM_IDS + (2 * jj + 1) * 4);
                const float* sL = EL + (size_t)id0 * DDIM + (c & 1) * 64;
                const float* sR = ER + (size_t)id1 * DDIM + (c & 1) * 64;
#pragma unroll
                for (int g = 0; g < 4; g++) {
                    int col0 = half * 32 + g * 8;
                    float4 l0 = *(const float4*)(sL + col0);
                    float4 l1 = *(const float4*)(sL + col0 + 4);
                    float4 r0 = *(const float4*)(sR + col0);
                    float4 r1 = *(const float4*)(sR + col0 + 4);
                    uint32_t bb = sb + SM_BIAS + ((c & 1) * 64 + col0) * 4;
                    v[2*g].x = l0.x + r0.x + lds_f32(bb + 0);
                    v[2*g].y = l0.y + r0.y + lds_f32(bb + 4);
                    v[2*g].z = l0.z + r0.z + lds_f32(bb + 8);
                    v[2*g].w = l0.w + r0.w + lds_f32(bb + 12);
                    v[2*g+1].x = l1.x + r1.x + lds_f32(bb + 16);
                    v[2*g+1].y = l1.y + r1.y + lds_f32(bb + 20);
                    v[2*g+1].z = l1.z + r1.z + lds_f32(bb + 24);
                    v[2*g+1].w = l1.w + r1.w + lds_f32(bb + 28);
                }
            } else {
                const float* src = A + (size_t)(tileRow + r) * KDIM + c * 64;
#pragma unroll
                for (int g = 0; g < 4; g++) {
                    int col0 = half * 32 + g * 8;
                    v[2 * g]     = *(const float4*)(src + col0);
                    v[2 * g + 1] = *(const float4*)(src + col0 + 4);
                }
            }

            // deferred epilogue of previous tile
            if (c == 0 && havePrev) {
                mbar_wait(sb + SM_MBAR1, (loads1 - 1) & 1);   // prev tile's last commit
                fence_after();
                const int colbase = (wid >> 2) * 64;
                const int rowg = prevRow + (wid & 3) * 32 + lid;
                float* outp = C + (size_t)rowg * DDIM + colbase;
                const uint32_t dbase = tmem + prevP * 128 + colbase;
#pragma unroll
                for (int hh = 0; hh < 2; hh++) {
                    uint32_t d[32];
                    ldtm32(d, dbase + hh * 32);
                    wait_ld();
#pragma unroll
                    for (int u = 0; u < 8; u++) {
                        uint32_t bb = sb + SM_BIAS + (colbase + hh * 32 + u * 4) * 4;
                        float4 o;
                        o.x = __uint_as_float(d[4*u+0]) + lds_f32(bb + 0);
                        o.y = __uint_as_float(d[4*u+1]) + lds_f32(bb + 4);
                        o.z = __uint_as_float(d[4*u+2]) + lds_f32(bb + 8);
                        o.w = __uint_as_float(d[4*u+3]) + lds_f32(bb + 12);
                        *(float4*)(outp + hh * 32 + u * 4) = o;
                    }
                }
                fence_before();
            }

            uint32_t hiB = sb + SM_A + b * 32768, loB = hiB + 16384;
#pragma unroll
            for (int g = 0; g < 4; g++) {
                int col0 = half * 32 + g * 8;
                uint4 h, l; split8(v[2 * g], v[2 * g + 1], h, l);
                uint32_t off = swz(r * 128 + col0 * 2);
                sts128(hiB + off, h.x, h.y, h.z, h.w);
                sts128(loB + off, l.x, l.y, l.z, l.w);
            }
            fence_proxy_async_s();
            __syncthreads();

            if (wid == 0 && elect_one()) {
                uint32_t aHi = sb + SM_A + b * 32768;
                uint64_t adh = mk_desc(aHi), adl = mk_desc(aHi + 16384);
                uint64_t bdh = mk_desc(sb + SM_BHI + c * 16384);
                uint64_t bdl = mk_desc(sb + SM_BLO + c * 16384);
                uint32_t dA = tmem + p * 128;
#pragma unroll
                for (int ks = 0; ks < 4; ks++)
                    mma_f16_ss(dA, adh + 2 * ks, bdh + 2 * ks, IDESC_N128, (c > 0 || ks > 0) ? 1u : 0u);
#pragma unroll
                for (int ks = 0; ks < 4; ks++)
                    mma_f16_ss(dA, adh + 2 * ks, bdl + 2 * ks, IDESC_N128, 1u);
#pragma unroll
                for (int ks = 0; ks < 4; ks++)
                    mma_f16_ss(dA, adl + 2 * ks, bdh + 2 * ks, IDESC_N128, 1u);
                mma_commit(sb + (b ? SM_MBAR1 : SM_MBAR0));
            }
        }
        prevP = p; prevRow = tileRow; p ^= 1; havePrev = true;
    }

    if (havePrev) {   // final epilogue
        mbar_wait(sb + SM_MBAR1, (loads1 - 1) & 1);
        fence_after();
        const int colbase = (wid >> 2) * 64;
        const int rowg = prevRow + (wid & 3) * 32 + lid;
        float* outp = C + (size_t)rowg * DDIM + colbase;
        const uint32_t dbase = tmem + prevP * 128 + colbase;
#pragma unroll
        for (int hh = 0; hh < 2; hh++) {
            uint32_t d[32];
            ldtm32(d, dbase + hh * 32);
            wait_ld();
#pragma unroll
            for (int u = 0; u < 8; u++) {
                uint32_t bb = sb + SM_BIAS + (colbase + hh * 32 + u * 4) * 4;
                float4 o;
                o.x = __uint_as_float(d[4*u+0]) + lds_f32(bb + 0);
                o.y = __uint_as_float(d[4*u+1]) + lds_f32(bb + 4);
                o.z = __uint_as_float(d[4*u+2]) + lds_f32(bb + 8);
                o.w = __uint_as_float(d[4*u+3]) + lds_f32(bb + 12);
                *(float4*)(outp + hh * 32 + u * 4) = o;
            }
        }
        fence_before();
    }
    __syncthreads();
    if (wid == 0) tmem_dealloc(tmem, 256);
#else
    (void)A; (void)ids; (void)EL; (void)ER; (void)W; (void)bias; (void)C; (void)numTiles;
#endif
}

// ---------------------------------------------------------------------------
// Host launcher
// ---------------------------------------------------------------------------
extern "C" void kernel_launch(void* const* d_in, const int* in_sizes, int n_in,
                              void* d_out, int out_size)
{
    (void)in_sizes; (void)n_in; (void)out_size;
    const int*   ids  = (const int*)d_in[0];
    const float* emb  = (const float*)d_in[1];
    const float* W    = (const float*)d_in[2];
    const float* bias = (const float*)d_in[3];
    float* out = (float*)d_out;

    static bool attr_set = false;
    if (!attr_set) {
        cudaFuncSetAttribute(precompute_tc, cudaFuncAttributeMaxDynamicSharedMemorySize, DYN_SMEM);
        cudaFuncSetAttribute(level_tc<0>,   cudaFuncAttributeMaxDynamicSharedMemorySize, DYN_SMEM);
        cudaFuncSetAttribute(level_tc<1>,   cudaFuncAttributeMaxDynamicSharedMemorySize, DYN_SMEM);
        attr_set = true;
    }

    float *bufA, *bufB, *elp, *erp;
    cudaGetSymbolAddress((void**)&bufA, g_bufA);
    cudaGetSymbolAddress((void**)&bufB, g_bufB);
    cudaGetSymbolAddress((void**)&elp,  g_EL);
    cudaGetSymbolAddress((void**)&erp,  g_ER);

    // 1) EL/ER precompute over vocab (782 tiles)
    precompute_tc<<<148, NTHREADS, DYN_SMEM>>>(emb, W, elp, erp, VOCABPAD / TILE_M);

    // 2) fused levels 1+2: output M = B*L/4 = 131072 rows
    int M = (BATCH * SEQ) / 4;
    level_tc<1><<<148, NTHREADS, DYN_SMEM>>>(nullptr, ids, elp, erp, W, bias, bufA, M / TILE_M);

    // 3) levels 3..11
    float* cur = bufA;
    float* nxt = bufB;
    int nodes = M;
    while (nodes > BATCH) {
        int Mo = nodes / 2;
        int tiles = Mo / TILE_M;
        int grid = tiles < 148 ? tiles : 148;
        float* dst = (Mo == BATCH) ? out : nxt;
        level_tc<0><<<grid, NTHREADS, DYN_SMEM>>>(cur, nullptr, nullptr, nullptr, W, bias, dst, tiles);
        float* t = cur; cur = nxt; nxt = t;
        nodes = Mo;
    }
}

// round 5
// speedup vs baseline: 2.3503x; 1.1171x over previous
#include <cuda_runtime.h>
#include <cstdint>

#define VOCAB    100000
#define VOCABPAD 100096                 // 782 tiles of 128
#define DDIM     128
#define KDIM     256
#define BATCH    256
#define SEQ      2048

#define NTHREADS 256
#define NPROD    224                    // warps 0-6 produce
#define TILE_M   128
#define NSTAGE   3

#if !defined(__CUDA_ARCH__) || defined(__CUDA_ARCH_FEAT_SM103_ALL) || \
    (defined(__CUDA_ARCH_SPECIFIC__) && (__CUDA_ARCH_SPECIFIC__ == 1030))
#define HAS_TCGEN05 1
#else
#define HAS_TCGEN05 0
#endif

// ---- SMEM frame (offsets from 1KB-aligned base) ----
// B: hi @0 (level: 4 chunks x 16KB | pre: 2 chunks x 32KB), lo @65536
#define SM_B     0
#define SM_A     131072                 // 3 stages x 32KB (hi 16KB + lo 16KB)
#define SM_HDR   229376
#define SM_TMEMP (SM_HDR + 0)
#define SM_FULL(s)  (SM_HDR + 16 + (s) * 8)
#define SM_EMPTY(s) (SM_HDR + 48 + (s) * 8)
#define SM_EPI(p)   (SM_HDR + 80 + (p) * 8)
#define SM_EPID(p)  (SM_HDR + 96 + (p) * 8)
#define SM_BIAS  (SM_HDR + 128)         // 512B
#define DYN_SMEM 231424

#define IDESC_N128 0x8200490u           // bf16->f32, M=128, N=128
#define IDESC_N256 0x8400490u           // bf16->f32, M=128, N=256

__device__ float g_bufA[131072 * 128];
__device__ float g_bufB[65536 * 128];
__device__ float g_EL[VOCABPAD * 128];
__device__ float g_ER[VOCABPAD * 128];

// ---------------- PTX helpers ----------------
__device__ __forceinline__ uint32_t smem_u32(const void* p) {
    uint32_t a;
    asm("{ .reg .u64 t; cvta.to.shared.u64 t, %1; cvt.u32.u64 %0, t; }" : "=r"(a) : "l"(p));
    return a;
}
__device__ __forceinline__ bool elect_one() {
    uint32_t pred;
    asm volatile("{ .reg .pred p; elect.sync _|p, 0xFFFFFFFF; selp.b32 %0, 1, 0, p; }" : "=r"(pred));
    return pred != 0;
}
__device__ __forceinline__ void sts128(uint32_t a, uint32_t x, uint32_t y, uint32_t z, uint32_t w) {
    asm volatile("st.shared.v4.b32 [%0], {%1,%2,%3,%4};" :: "r"(a), "r"(x), "r"(y), "r"(z), "r"(w) : "memory");
}
__device__ __forceinline__ int lds_s32(uint32_t a) {
    int v; asm volatile("ld.shared.b32 %0, [%1];" : "=r"(v) : "r"(a)); return v;
}
__device__ __forceinline__ float4 lds_f32x4(uint32_t a) {
    float4 v;
    asm volatile("ld.shared.v4.f32 {%0,%1,%2,%3}, [%4];"
                 : "=f"(v.x), "=f"(v.y), "=f"(v.z), "=f"(v.w) : "r"(a));
    return v;
}
__device__ __forceinline__ void sts_b32(uint32_t a, uint32_t v) {
    asm volatile("st.shared.b32 [%0], %1;" :: "r"(a), "r"(v) : "memory");
}
__device__ __forceinline__ void mbar_init(uint32_t a, uint32_t c) {
    asm volatile("mbarrier.init.shared.b64 [%0], %1;" :: "r"(a), "r"(c) : "memory");
}
__device__ __forceinline__ void mbar_arrive(uint32_t a) {
    asm volatile("mbarrier.arrive.shared.b64 _, [%0];" :: "r"(a) : "memory");
}
__device__ __forceinline__ void fence_proxy_async_s() {
    asm volatile("fence.proxy.async.shared::cta;" ::: "memory");
}

#if HAS_TCGEN05
__device__ __forceinline__ void mbar_wait(uint32_t a, uint32_t parity) {
    asm volatile(
        "{\n\t.reg .pred P;\n\t"
        "W%=:\n\t"
        "mbarrier.try_wait.parity.acquire.cta.shared::cta.b64 P, [%0], %1, 0x989680;\n\t"
        "@P bra.uni D%=;\n\t"
        "bra.uni W%=;\n\t"
        "D%=:\n\t}"
        :: "r"(a), "r"(parity) : "memory");
}
__device__ __forceinline__ void tmem_alloc(uint32_t dst, uint32_t n) {
    asm volatile("tcgen05.alloc.cta_group::1.sync.aligned.shared::cta.b32 [%0], %1;"
                 :: "r"(dst), "r"(n) : "memory");
}
__device__ __forceinline__ void tmem_relinquish() {
    asm volatile("tcgen05.relinquish_alloc_permit.cta_group::1.sync.aligned;");
}
__device__ __forceinline__ void tmem_dealloc(uint32_t t, uint32_t n) {
    asm volatile("tcgen05.dealloc.cta_group::1.sync.aligned.b32 %0, %1;" :: "r"(t), "r"(n));
}
__device__ __forceinline__ void mma_f16_ss(uint32_t d, uint64_t ad, uint64_t bd, uint32_t idesc, uint32_t en) {
    asm volatile(
        "{\n\t.reg .pred p;\n\tsetp.ne.u32 p, %4, 0;\n\t"
        "tcgen05.mma.cta_group::1.kind::f16 [%0], %1, %2, %3, {%5,%5,%5,%5}, p;\n\t}"
        :: "r"(d), "l"(ad), "l"(bd), "r"(idesc), "r"(en), "r"(0u) : "memory");
}
__device__ __forceinline__ void mma_commit(uint32_t mbar) {
    asm volatile("tcgen05.commit.cta_group::1.mbarrier::arrive::one.shared::cluster.b64 [%0];"
                 :: "r"(mbar) : "memory");
}
__device__ __forceinline__ void fence_after()  { asm volatile("tcgen05.fence::after_thread_sync;"  ::: "memory"); }
__device__ __forceinline__ void fence_before() { asm volatile("tcgen05.fence::before_thread_sync;" ::: "memory"); }
__device__ __forceinline__ void wait_ld()      { asm volatile("tcgen05.wait::ld.sync.aligned;"     ::: "memory"); }
__device__ __forceinline__ void ldtm32(uint32_t* r, uint32_t ta) {
    asm volatile(
        "tcgen05.ld.sync.aligned.32x32b.x32.b32 "
        "{%0, %1, %2, %3, %4, %5, %6, %7, "
        " %8, %9, %10, %11, %12, %13, %14, %15, "
        " %16, %17, %18, %19, %20, %21, %22, %23, "
        " %24, %25, %26, %27, %28, %29, %30, %31}, [%32];"
        : "=r"(r[0]), "=r"(r[1]), "=r"(r[2]), "=r"(r[3]),
          "=r"(r[4]), "=r"(r[5]), "=r"(r[6]), "=r"(r[7]),
          "=r"(r[8]), "=r"(r[9]), "=r"(r[10]), "=r"(r[11]),
          "=r"(r[12]), "=r"(r[13]), "=r"(r[14]), "=r"(r[15]),
          "=r"(r[16]), "=r"(r[17]), "=r"(r[18]), "=r"(r[19]),
          "=r"(r[20]), "=r"(r[21]), "=r"(r[22]), "=r"(r[23]),
          "=r"(r[24]), "=r"(r[25]), "=r"(r[26]), "=r"(r[27]),
          "=r"(r[28]), "=r"(r[29]), "=r"(r[30]), "=r"(r[31])
        : "r"(ta));
}
#endif // HAS_TCGEN05

__device__ __forceinline__ uint32_t swz(uint32_t off) { return off ^ ((off >> 3) & 0x70); }

__device__ __forceinline__ uint64_t mk_desc(uint32_t addr) {
    const uint64_t base = (uint64_t(2) << 61) | (uint64_t(1) << 46) |
                          (uint64_t(64) << 32) | (uint64_t(1) << 16);
    return base | ((uint64_t)(addr >> 4) & 0x3FFF);
}

// split 8 fp32 -> bf16 hi + exact-residual bf16 lo
__device__ __forceinline__ void split8(const float4& v0, const float4& v1, uint4& h, uint4& l) {
    float f[8] = {v0.x, v0.y, v0.z, v0.w, v1.x, v1.y, v1.z, v1.w};
    uint32_t hh[4], ll[4];
#pragma unroll
    for (int q = 0; q < 4; q++) {
        float a = f[2 * q], b = f[2 * q + 1];
        uint32_t hv;
        asm("cvt.rn.bf16x2.f32 %0, %1, %2;" : "=r"(hv) : "f"(b), "f"(a));
        hh[q] = hv;
        float ha = __uint_as_float(hv << 16);
        float hb = __uint_as_float(hv & 0xFFFF0000u);
        asm("cvt.rn.bf16x2.f32 %0, %1, %2;" : "=r"(ll[q]) : "f"(b - hb), "f"(a - ha));
    }
    h = make_uint4(hh[0], hh[1], hh[2], hh[3]);
    l = make_uint4(ll[0], ll[1], ll[2], ll[3]);
}

// ---------------------------------------------------------------------------
// Level GEMM, warp-specialized. C[M x 128] = A[M x 256] @ W^T + bias
// MODE 0: A from memory.  MODE 1: A row m = [o(2m); o(2m+1)],
//   o(j) = EL[ids[2j]] + ER[ids[2j+1]] + bias   (fused levels 1+2)
// ---------------------------------------------------------------------------
template <int MODE>
__global__ __launch_bounds__(NTHREADS, 1)
void level_tc(const float* __restrict__ A, const int* __restrict__ ids,
              const float* __restrict__ EL, const float* __restrict__ ER,
              const float* __restrict__ W, const float* __restrict__ bias,
              float* __restrict__ C, int numTiles)
{
#if HAS_TCGEN05
    extern __shared__ char dsm[];
    const uint32_t sb = (smem_u32(dsm) + 1023) & ~1023u;
    const int tid = threadIdx.x, wid = tid >> 5, lid = tid & 31;

    if (tid == 0) {
#pragma unroll
        for (int s = 0; s < NSTAGE; s++) { mbar_init(SM_FULL(s) + sb, NPROD); mbar_init(SM_EMPTY(s) + sb, 1); }
#pragma unroll
        for (int p = 0; p < 2; p++) { mbar_init(SM_EPI(p) + sb, 1); mbar_init(SM_EPID(p) + sb, 128); }
    }
    if (tid < 128) sts_b32(sb + SM_BIAS + tid * 4, __float_as_uint(bias[tid]));

    // B = W (128 x 256) split into 4 K-chunks of 64, SW128
    {
        const int n = tid >> 1, h2 = tid & 1;
#pragma unroll
        for (int g = 0; g < 16; g++) {
            int k0 = h2 * 128 + g * 8;
            float4 v0 = *(const float4*)(W + (size_t)n * KDIM + k0);
            float4 v1 = *(const float4*)(W + (size_t)n * KDIM + k0 + 4);
            uint4 h, l; split8(v0, v1, h, l);
            uint32_t off = (k0 >> 6) * 16384 + swz(n * 128 + (k0 & 63) * 2);
            sts128(sb + SM_B + off, h.x, h.y, h.z, h.w);
            sts128(sb + SM_B + 65536 + off, l.x, l.y, l.z, l.w);
        }
    }
    fence_proxy_async_s();
    __syncthreads();
    if (wid == 0) { tmem_alloc(sb + SM_TMEMP, 256); tmem_relinquish(); }
    __syncthreads();
    const uint32_t tmem = (uint32_t)lds_s32(sb + SM_TMEMP);

    const bool mmaLead = (wid == 7) && elect_one();

    int uc[NSTAGE] = {0, 0, 0};   // producer stage use counts
    int fc[NSTAGE] = {0, 0, 0};   // mma full consume counts
    int tp[2] = {0, 0};           // mma D-buffer use counts
    int epc[2] = {0, 0};          // epilogue EPI consume counts
    int tl = 0, prevRow = 0;

    for (int tile = blockIdx.x; tile < numTiles; tile += gridDim.x) {
        const int tileRow = tile * TILE_M;

        if (tid < NPROD) {
            // ---------------- producers ----------------
#pragma unroll
            for (int c = 0; c < 4; c++) {
                const int s = (tl * 4 + c) % NSTAGE;
                if (uc[s] > 0) mbar_wait(sb + SM_EMPTY(s), (uc[s] - 1) & 1);
                uc[s]++;
                const uint32_t hiB = sb + SM_A + s * 32768, loB = hiB + 16384;
                for (int i = tid; i < 1024; i += NPROD) {
                    const int row = i >> 3, oct = i & 7;
                    float4 v0, v1;
                    if (MODE == 1) {
                        const int j = 2 * (tileRow + row) + (c >> 1);
                        const int idL = ids[2 * j], idR = ids[2 * j + 1];
                        const int sub = (c & 1) * 64 + oct * 8;
                        const float* pl = EL + (size_t)idL * DDIM + sub;
                        const float* pr = ER + (size_t)idR * DDIM + sub;
                        float4 l0 = *(const float4*)pl,      r0 = *(const float4*)pr;
                        float4 l1 = *(const float4*)(pl + 4), r1 = *(const float4*)(pr + 4);
                        float4 b0 = lds_f32x4(sb + SM_BIAS + sub * 4);
                        float4 b1 = lds_f32x4(sb + SM_BIAS + (sub + 4) * 4);
                        v0.x = l0.x + r0.x + b0.x; v0.y = l0.y + r0.y + b0.y;
                        v0.z = l0.z + r0.z + b0.z; v0.w = l0.w + r0.w + b0.w;
                        v1.x = l1.x + r1.x + b1.x; v1.y = l1.y + r1.y + b1.y;
                        v1.z = l1.z + r1.z + b1.z; v1.w = l1.w + r1.w + b1.w;
                    } else {
                        const float* src = A + (size_t)(tileRow + row) * KDIM + c * 64 + oct * 8;
                        v0 = *(const float4*)src;
                        v1 = *(const float4*)(src + 4);
                    }
                    uint4 h, l; split8(v0, v1, h, l);
                    const uint32_t off = swz(row * 128 + oct * 16);
                    sts128(hiB + off, h.x, h.y, h.z, h.w);
                    sts128(loB + off, l.x, l.y, l.z, l.w);
                }
                fence_proxy_async_s();
                mbar_arrive(sb + SM_FULL(s));
            }
            // ---------------- epilogue of previous tile (warps 0-3) ----------------
            if (wid < 4 && tl >= 1) {
                const int p = (tl - 1) & 1;
                mbar_wait(sb + SM_EPI(p), epc[p] & 1); epc[p]++;
                fence_after();
                const int rowg = prevRow + wid * 32 + lid;
                float* outp = C + (size_t)rowg * DDIM;
#pragma unroll
                for (int q = 0; q < 4; q++) {
                    uint32_t d[32];
                    ldtm32(d, tmem + p * 128 + q * 32);
                    wait_ld();
#pragma unroll
                    for (int u = 0; u < 8; u++) {
                        float4 bv = lds_f32x4(sb + SM_BIAS + (q * 32 + u * 4) * 4);
                        float4 o;
                        o.x = __uint_as_float(d[4*u+0]) + bv.x;
                        o.y = __uint_as_float(d[4*u+1]) + bv.y;
                        o.z = __uint_as_float(d[4*u+2]) + bv.z;
                        o.w = __uint_as_float(d[4*u+3]) + bv.w;
                        *(float4*)(outp + q * 32 + u * 4) = o;
                    }
                }
                fence_before();
                mbar_arrive(sb + SM_EPID(p));
            }
        } else if (mmaLead) {
            // ---------------- MMA issuer ----------------
            const int p = tl & 1;
            if (tp[p] > 0) mbar_wait(sb + SM_EPID(p), (tp[p] - 1) & 1);
            tp[p]++;
            const uint32_t dA = tmem + p * 128;
#pragma unroll
            for (int c = 0; c < 4; c++) {
                const int s = (tl * 4 + c) % NSTAGE;
                mbar_wait(sb + SM_FULL(s), fc[s] & 1); fc[s]++;
                const uint32_t aHi = sb + SM_A + s * 32768;
                const uint64_t adh = mk_desc(aHi), adl = mk_desc(aHi + 16384);
                const uint64_t bdh = mk_desc(sb + SM_B + c * 16384);
                const uint64_t bdl = mk_desc(sb + SM_B + 65536 + c * 16384);
#pragma unroll
                for (int ks = 0; ks < 4; ks++)
                    mma_f16_ss(dA, adh + 2 * ks, bdh + 2 * ks, IDESC_N128, (c > 0 || ks > 0) ? 1u : 0u);
#pragma unroll
                for (int ks = 0; ks < 4; ks++)
                    mma_f16_ss(dA, adh + 2 * ks, bdl + 2 * ks, IDESC_N128, 1u);
#pragma unroll
                for (int ks = 0; ks < 4; ks++)
                    mma_f16_ss(dA, adl + 2 * ks, bdh + 2 * ks, IDESC_N128, 1u);
                mma_commit(sb + SM_EMPTY(s));
            }
            mma_commit(sb + SM_EPI(p));
        }
        prevRow = tileRow; tl++;
    }

    // final epilogue (warps 0-3)
    if (wid < 4 && tl >= 1) {
        const int p = (tl - 1) & 1;
        mbar_wait(sb + SM_EPI(p), epc[p] & 1); epc[p]++;
        fence_after();
        const int rowg = prevRow + wid * 32 + lid;
        float* outp = C + (size_t)rowg * DDIM;
#pragma unroll
        for (int q = 0; q < 4; q++) {
            uint32_t d[32];
            ldtm32(d, tmem + p * 128 + q * 32);
            wait_ld();
#pragma unroll
            for (int u = 0; u < 8; u++) {
                float4 bv = lds_f32x4(sb + SM_BIAS + (q * 32 + u * 4) * 4);
                float4 o;
                o.x = __uint_as_float(d[4*u+0]) + bv.x;
                o.y = __uint_as_float(d[4*u+1]) + bv.y;
                o.z = __uint_as_float(d[4*u+2]) + bv.z;
                o.w = __uint_as_float(d[4*u+3]) + bv.w;
                *(float4*)(outp + q * 32 + u * 4) = o;
            }
        }
        fence_before();
    }
    __syncthreads();
    if (wid == 0) tmem_dealloc(tmem, 256);
#else
    (void)A; (void)ids; (void)EL; (void)ER; (void)W; (void)bias; (void)C; (void)numTiles;
#endif
}

// ---------------------------------------------------------------------------
// Precompute (warp-specialized): EL = emb @ W[:, :128]^T, ER = emb @ W[:, 128:]^T
// N=256 fused; K=128 in 2 chunks of 64; D double-buffered at cols 0 / 256.
// ---------------------------------------------------------------------------
__global__ __launch_bounds__(NTHREADS, 1)
void precompute_tc(const float* __restrict__ emb, const float* __restrict__ W,
                   float* __restrict__ EL, float* __restrict__ ER, int numTiles)
{
#if HAS_TCGEN05
    extern __shared__ char dsm[];
    const uint32_t sb = (smem_u32(dsm) + 1023) & ~1023u;
    const int tid = threadIdx.x, wid = tid >> 5, lid = tid & 31;

    if (tid == 0) {
#pragma unroll
        for (int s = 0; s < NSTAGE; s++) { mbar_init(SM_FULL(s) + sb, NPROD); mbar_init(SM_EMPTY(s) + sb, 1); }
#pragma unroll
        for (int p = 0; p < 2; p++) { mbar_init(SM_EPI(p) + sb, 1); mbar_init(SM_EPID(p) + sb, 128); }
    }

    // B (256 x 128): row n<128 -> W[n][k] (EL), n>=128 -> W[n-128][128+k] (ER); 2 chunks of K=64
    {
        const int n = tid;
        const float* wrow = W + (size_t)(n & 127) * KDIM + (n >> 7) * 128;
#pragma unroll
        for (int g = 0; g < 16; g++) {
            int k0 = g * 8;
            float4 v0 = *(const float4*)(wrow + k0);
            float4 v1 = *(const float4*)(wrow + k0 + 4);
            uint4 h, l; split8(v0, v1, h, l);
            uint32_t off = (k0 >> 6) * 32768 + swz(n * 128 + (k0 & 63) * 2);
            sts128(sb + SM_B + off, h.x, h.y, h.z, h.w);
            sts128(sb + SM_B + 65536 + off, l.x, l.y, l.z, l.w);
        }
    }
    fence_proxy_async_s();
    __syncthreads();
    if (wid == 0) { tmem_alloc(sb + SM_TMEMP, 512); tmem_relinquish(); }
    __syncthreads();
    const uint32_t tmem = (uint32_t)lds_s32(sb + SM_TMEMP);

    const bool mmaLead = (wid == 7) && elect_one();

    int uc[NSTAGE] = {0, 0, 0};
    int fc[NSTAGE] = {0, 0, 0};
    int tp[2] = {0, 0};
    int epc[2] = {0, 0};
    int tl = 0, prevRow = 0;

    for (int tile = blockIdx.x; tile < numTiles; tile += gridDim.x) {
        const int tileRow = tile * TILE_M;

        if (tid < NPROD) {
#pragma unroll
            for (int c = 0; c < 2; c++) {
                const int s = (tl * 2 + c) % NSTAGE;
                if (uc[s] > 0) mbar_wait(sb + SM_EMPTY(s), (uc[s] - 1) & 1);
                uc[s]++;
                const uint32_t hiB = sb + SM_A + s * 32768, loB = hiB + 16384;
                for (int i = tid; i < 1024; i += NPROD) {
                    const int row = i >> 3, oct = i & 7;
                    int er = tileRow + row; if (er > VOCAB - 1) er = VOCAB - 1;
                    const float* src = emb + (size_t)er * DDIM + c * 64 + oct * 8;
                    float4 v0 = *(const float4*)src;
                    float4 v1 = *(const float4*)(src + 4);
                    uint4 h, l; split8(v0, v1, h, l);
                    const uint32_t off = swz(row * 128 + oct * 16);
                    sts128(hiB + off, h.x, h.y, h.z, h.w);
                    sts128(loB + off, l.x, l.y, l.z, l.w);
                }
                fence_proxy_async_s();
                mbar_arrive(sb + SM_FULL(s));
            }
            if (wid < 4 && tl >= 1) {
                const int p = (tl - 1) & 1;
                mbar_wait(sb + SM_EPI(p), epc[p] & 1); epc[p]++;
                fence_after();
                const int rowg = prevRow + wid * 32 + lid;
#pragma unroll
                for (int q = 0; q < 8; q++) {
                    uint32_t d[32];
                    ldtm32(d, tmem + p * 256 + q * 32);
                    wait_ld();
                    const int col0 = q * 32;
                    float* dst = (col0 < 128 ? EL + (size_t)rowg * DDIM + col0
                                             : ER + (size_t)rowg * DDIM + (col0 - 128));
#pragma unroll
                    for (int u = 0; u < 8; u++)
                        *(float4*)(dst + u * 4) =
                            make_float4(__uint_as_float(d[4*u+0]), __uint_as_float(d[4*u+1]),
                                        __uint_as_float(d[4*u+2]), __uint_as_float(d[4*u+3]));
                }
                fence_before();
                mbar_arrive(sb + SM_EPID(p));
            }
        } else if (mmaLead) {
            const int p = tl & 1;
            if (tp[p] > 0) mbar_wait(sb + SM_EPID(p), (tp[p] - 1) & 1);
            tp[p]++;
            const uint32_t dA = tmem + p * 256;
#pragma unroll
            for (int c = 0; c < 2; c++) {
                const int s = (tl * 2 + c) % NSTAGE;
                mbar_wait(sb + SM_FULL(s), fc[s] & 1); fc[s]++;
                const uint32_t aHi = sb + SM_A + s * 32768;
                const uint64_t adh = mk_desc(aHi), adl = mk_desc(aHi + 16384);
                const uint64_t bdh = mk_desc(sb + SM_B + c * 32768);
                const uint64_t bdl = mk_desc(sb + SM_B + 65536 + c * 32768);
#pragma unroll
                for (int ks = 0; ks < 4; ks++)
                    mma_f16_ss(dA, adh + 2 * ks, bdh + 2 * ks, IDESC_N256, (c > 0 || ks > 0) ? 1u : 0u);
#pragma unroll
                for (int ks = 0; ks < 4; ks++)
                    mma_f16_ss(dA, adh + 2 * ks, bdl + 2 * ks, IDESC_N256, 1u);
#pragma unroll
                for (int ks = 0; ks < 4; ks++)
                    mma_f16_ss(dA, adl + 2 * ks, bdh + 2 * ks, IDESC_N256, 1u);
                mma_commit(sb + SM_EMPTY(s));
            }
            mma_commit(sb + SM_EPI(p));
        }
        prevRow = tileRow; tl++;
    }

    if (wid < 4 && tl >= 1) {
        const int p = (tl - 1) & 1;
        mbar_wait(sb + SM_EPI(p), epc[p] & 1); epc[p]++;
        fence_after();
        const int rowg = prevRow + wid * 32 + lid;
#pragma unroll
        for (int q = 0; q < 8; q++) {
            uint32_t d[32];
            ldtm32(d, tmem + p * 256 + q * 32);
            wait_ld();
            const int col0 = q * 32;
            float* dst = (col0 < 128 ? EL + (size_t)rowg * DDIM + col0
                                     : ER + (size_t)rowg * DDIM + (col0 - 128));
#pragma unroll
            for (int u = 0; u < 8; u++)
                *(float4*)(dst + u * 4) =
                    make_float4(__uint_as_float(d[4*u+0]), __uint_as_float(d[4*u+1]),
                                __uint_as_float(d[4*u+2]), __uint_as_float(d[4*u+3]));
        }
        fence_before();
    }
    __syncthreads();
    if (wid == 0) tmem_dealloc(tmem, 512);
#else
    (void)emb; (void)W; (void)EL; (void)ER; (void)numTiles;
#endif
}

// ---------------------------------------------------------------------------
// Host launcher
// ---------------------------------------------------------------------------
extern "C" void kernel_launch(void* const* d_in, const int* in_sizes, int n_in,
                              void* d_out, int out_size)
{
    (void)in_sizes; (void)n_in; (void)out_size;
    const int*   ids  = (const int*)d_in[0];
    const float* emb  = (const float*)d_in[1];
    const float* W    = (const float*)d_in[2];
    const float* bias = (const float*)d_in[3];
    float* out = (float*)d_out;

    static bool attr_set = false;
    if (!attr_set) {
        cudaFuncSetAttribute(precompute_tc, cudaFuncAttributeMaxDynamicSharedMemorySize, DYN_SMEM);
        cudaFuncSetAttribute(level_tc<0>,   cudaFuncAttributeMaxDynamicSharedMemorySize, DYN_SMEM);
        cudaFuncSetAttribute(level_tc<1>,   cudaFuncAttributeMaxDynamicSharedMemorySize, DYN_SMEM);
        attr_set = true;
    }

    float *bufA, *bufB, *elp, *erp;
    cudaGetSymbolAddress((void**)&bufA, g_bufA);
    cudaGetSymbolAddress((void**)&bufB, g_bufB);
    cudaGetSymbolAddress((void**)&elp,  g_EL);
    cudaGetSymbolAddress((void**)&erp,  g_ER);

    precompute_tc<<<148, NTHREADS, DYN_SMEM>>>(emb, W, elp, erp, VOCABPAD / TILE_M);

    int M = (BATCH * SEQ) / 4;   // fused levels 1+2 output rows
    level_tc<1><<<148, NTHREADS, DYN_SMEM>>>(nullptr, ids, elp, erp, W, bias, bufA, M / TILE_M);

    float* cur = bufA;
    float* nxt = bufB;
    int nodes = M;
    while (nodes > BATCH) {
        int Mo = nodes / 2;
        int tiles = Mo / TILE_M;
        int grid = tiles < 148 ? tiles : 148;
        float* dst = (Mo == BATCH) ? out : nxt;
        level_tc<0><<<grid, NTHREADS, DYN_SMEM>>>(cur, nullptr, nullptr, nullptr, W, bias, dst, tiles);
        float* t = cur; cur = nxt; nxt = t;
        nodes = Mo;
    }
}

// round 6
// speedup vs baseline: 3.0543x; 1.2996x over previous
#include <cuda_runtime.h>
#include <cstdint>

#define VOCAB    100000
#define VOCABPAD 100096
#define DDIM     128
#define KDIM     256
#define NTHREADS 256
#define NPROD    224
#define TILE_M   128
#define NSTAGE   3

#define NTREE    1022                   // 512+256+128+64+32+16+8+4+2
#define BLKB     131072u                // bytes per consumer-tile block (4 chunks x (hi+lo) 16KB)
#define CHB      32768u                 // bytes per chunk (hi 16KB + lo 16KB)

#if !defined(__CUDA_ARCH__) || defined(__CUDA_ARCH_FEAT_SM103_ALL) || \
    (defined(__CUDA_ARCH_SPECIFIC__) && (__CUDA_ARCH_SPECIFIC__ == 1030))
#define HAS_TCGEN05 1
#else
#define HAS_TCGEN05 0
#endif

// ---- SMEM frame (offsets from 1KB-aligned base) ----
#define SM_B     0                      // 4 chunks x 16KB hi  | pre: 2 x 32KB
#define SM_BLO   65536                  // lo mirror
#define SM_A     131072                 // 3 stages x 32KB (hi 16KB + lo 16KB)
#define SM_HDR   229376
#define SM_TMEMP (SM_HDR + 0)
#define SM_FULL(s)  (SM_HDR + 16 + (s) * 8)
#define SM_EMPTY(s) (SM_HDR + 48 + (s) * 8)
#define SM_EPI(p)   (SM_HDR + 80 + (p) * 8)
#define SM_EPID(p)  (SM_HDR + 96 + (p) * 8)
#define SM_BIAS  (SM_HDR + 128)
#define DYN_SMEM 231424

#define IDESC_N128 0x8200490u
#define IDESC_N256 0x8400490u

// level tile-count prefix sums (global tile ids, level-major)
__constant__ int c_off[10] = {0, 512, 768, 896, 960, 992, 1008, 1016, 1020, 1022};

// ---- device scratch ----
__device__ uint4 g_tree[NTREE * BLKB / 16];      // 134MB arena of chunked bf16 hi/lo blocks
__device__ int   g_flags[1024];
__device__ float g_EL[VOCABPAD * 128];
__device__ float g_ER[VOCABPAD * 128];

// ---------------- PTX helpers ----------------
__device__ __forceinline__ uint32_t smem_u32(const void* p) {
    uint32_t a;
    asm("{ .reg .u64 t; cvta.to.shared.u64 t, %1; cvt.u32.u64 %0, t; }" : "=r"(a) : "l"(p));
    return a;
}
__device__ __forceinline__ bool elect_one() {
    uint32_t pred;
    asm volatile("{ .reg .pred p; elect.sync _|p, 0xFFFFFFFF; selp.b32 %0, 1, 0, p; }" : "=r"(pred));
    return pred != 0;
}
__device__ __forceinline__ void sts128(uint32_t a, uint32_t x, uint32_t y, uint32_t z, uint32_t w) {
    asm volatile("st.shared.v4.b32 [%0], {%1,%2,%3,%4};" :: "r"(a), "r"(x), "r"(y), "r"(z), "r"(w) : "memory");
}
__device__ __forceinline__ int lds_s32(uint32_t a) {
    int v; asm volatile("ld.shared.b32 %0, [%1];" : "=r"(v) : "r"(a)); return v;
}
__device__ __forceinline__ float4 lds_f32x4(uint32_t a) {
    float4 v;
    asm volatile("ld.shared.v4.f32 {%0,%1,%2,%3}, [%4];"
                 : "=f"(v.x), "=f"(v.y), "=f"(v.z), "=f"(v.w) : "r"(a));
    return v;
}
__device__ __forceinline__ void sts_b32(uint32_t a, uint32_t v) {
    asm volatile("st.shared.b32 [%0], %1;" :: "r"(a), "r"(v) : "memory");
}
__device__ __forceinline__ void mbar_init(uint32_t a, uint32_t c) {
    asm volatile("mbarrier.init.shared.b64 [%0], %1;" :: "r"(a), "r"(c) : "memory");
}
__device__ __forceinline__ void mbar_arrive(uint32_t a) {
    asm volatile("mbarrier.arrive.shared.b64 _, [%0];" :: "r"(a) : "memory");
}
__device__ __forceinline__ void mbar_expect_tx(uint32_t a, uint32_t bytes) {
    asm volatile("mbarrier.arrive.expect_tx.shared.b64 _, [%0], %1;" :: "r"(a), "r"(bytes) : "memory");
}
__device__ __forceinline__ void bulk_g2s(uint32_t dst, const char* src, uint32_t bytes, uint32_t mbar) {
    asm volatile("cp.async.bulk.shared::cluster.global.mbarrier::complete_tx::bytes [%0], [%1], %2, [%3];"
                 :: "r"(dst), "l"(src), "r"(bytes), "r"(mbar) : "memory");
}
__device__ __forceinline__ void fence_proxy_async_s() {
    asm volatile("fence.proxy.async.shared::cta;" ::: "memory");
}
__device__ __forceinline__ int ld_acq(const int* p) {
    int v; asm volatile("ld.acquire.gpu.global.b32 %0, [%1];" : "=r"(v) : "l"(p) : "memory");
    return v;
}
__device__ __forceinline__ void red_rel_add1(int* p) {
    asm volatile("red.release.gpu.global.add.s32 [%0], 1;" :: "l"(p) : "memory");
}
__device__ __forceinline__ void nsleep() { asm volatile("nanosleep.u32 128;" ::: ); }

#if HAS_TCGEN05
__device__ __forceinline__ void mbar_wait(uint32_t a, uint32_t parity) {
    asm volatile(
        "{\n\t.reg .pred P;\n\t"
        "W%=:\n\t"
        "mbarrier.try_wait.parity.acquire.cta.shared::cta.b64 P, [%0], %1, 0x989680;\n\t"
        "@P bra.uni D%=;\n\t"
        "bra.uni W%=;\n\t"
        "D%=:\n\t}"
        :: "r"(a), "r"(parity) : "memory");
}
__device__ __forceinline__ void tmem_alloc(uint32_t dst, uint32_t n) {
    asm volatile("tcgen05.alloc.cta_group::1.sync.aligned.shared::cta.b32 [%0], %1;"
                 :: "r"(dst), "r"(n) : "memory");
}
__device__ __forceinline__ void tmem_relinquish() {
    asm volatile("tcgen05.relinquish_alloc_permit.cta_group::1.sync.aligned;");
}
__device__ __forceinline__ void tmem_dealloc(uint32_t t, uint32_t n) {
    asm volatile("tcgen05.dealloc.cta_group::1.sync.aligned.b32 %0, %1;" :: "r"(t), "r"(n));
}
__device__ __forceinline__ void mma_f16_ss(uint32_t d, uint64_t ad, uint64_t bd, uint32_t idesc, uint32_t en) {
    asm volatile(
        "{\n\t.reg .pred p;\n\tsetp.ne.u32 p, %4, 0;\n\t"
        "tcgen05.mma.cta_group::1.kind::f16 [%0], %1, %2, %3, {%5,%5,%5,%5}, p;\n\t}"
        :: "r"(d), "l"(ad), "l"(bd), "r"(idesc), "r"(en), "r"(0u) : "memory");
}
__device__ __forceinline__ void mma_commit(uint32_t mbar) {
    asm volatile("tcgen05.commit.cta_group::1.mbarrier::arrive::one.shared::cluster.b64 [%0];"
                 :: "r"(mbar) : "memory");
}
__device__ __forceinline__ void fence_after()  { asm volatile("tcgen05.fence::after_thread_sync;"  ::: "memory"); }
__device__ __forceinline__ void fence_before() { asm volatile("tcgen05.fence::before_thread_sync;" ::: "memory"); }
__device__ __forceinline__ void wait_ld()      { asm volatile("tcgen05.wait::ld.sync.aligned;"     ::: "memory"); }
__device__ __forceinline__ void ldtm32(uint32_t* r, uint32_t ta) {
    asm volatile(
        "tcgen05.ld.sync.aligned.32x32b.x32.b32 "
        "{%0, %1, %2, %3, %4, %5, %6, %7, "
        " %8, %9, %10, %11, %12, %13, %14, %15, "
        " %16, %17, %18, %19, %20, %21, %22, %23, "
        " %24, %25, %26, %27, %28, %29, %30, %31}, [%32];"
        : "=r"(r[0]), "=r"(r[1]), "=r"(r[2]), "=r"(r[3]),
          "=r"(r[4]), "=r"(r[5]), "=r"(r[6]), "=r"(r[7]),
          "=r"(r[8]), "=r"(r[9]), "=r"(r[10]), "=r"(r[11]),
          "=r"(r[12]), "=r"(r[13]), "=r"(r[14]), "=r"(r[15]),
          "=r"(r[16]), "=r"(r[17]), "=r"(r[18]), "=r"(r[19]),
          "=r"(r[20]), "=r"(r[21]), "=r"(r[22]), "=r"(r[23]),
          "=r"(r[24]), "=r"(r[25]), "=r"(r[26]), "=r"(r[27]),
          "=r"(r[28]), "=r"(r[29]), "=r"(r[30]), "=r"(r[31])
        : "r"(ta));
}
#endif // HAS_TCGEN05

__device__ __forceinline__ uint32_t swz(uint32_t off) { return off ^ ((off >> 3) & 0x70); }

__device__ __forceinline__ uint64_t mk_desc(uint32_t addr) {
    const uint64_t base = (uint64_t(2) << 61) | (uint64_t(1) << 46) |
                          (uint64_t(64) << 32) | (uint64_t(1) << 16);
    return base | ((uint64_t)(addr >> 4) & 0x3FFF);
}

// split 8 fp32 -> bf16 hi + exact-residual bf16 lo
__device__ __forceinline__ void split8(const float4& v0, const float4& v1, uint4& h, uint4& l) {
    float f[8] = {v0.x, v0.y, v0.z, v0.w, v1.x, v1.y, v1.z, v1.w};
    uint32_t hh[4], ll[4];
#pragma unroll
    for (int q = 0; q < 4; q++) {
        float a = f[2 * q], b = f[2 * q + 1];
        uint32_t hv;
        asm("cvt.rn.bf16x2.f32 %0, %1, %2;" : "=r"(hv) : "f"(b), "f"(a));
        hh[q] = hv;
        float ha = __uint_as_float(hv << 16);
        float hb = __uint_as_float(hv & 0xFFFF0000u);
        asm("cvt.rn.bf16x2.f32 %0, %1, %2;" : "=r"(ll[q]) : "f"(b - hb), "f"(a - ha));
    }
    h = make_uint4(hh[0], hh[1], hh[2], hh[3]);
    l = make_uint4(ll[0], ll[1], ll[2], ll[3]);
}

#if HAS_TCGEN05
// 12 split-MMAs for one K=64 chunk (A in stage s, B chunk c); first: fresh accumulate
__device__ __forceinline__ void mma_chunk(uint32_t dA, uint32_t sb, int s, int c, bool first) {
    const uint32_t aHi = sb + SM_A + s * 32768;
    const uint64_t adh = mk_desc(aHi), adl = mk_desc(aHi + 16384);
    const uint64_t bdh = mk_desc(sb + SM_B + c * 16384);
    const uint64_t bdl = mk_desc(sb + SM_BLO + c * 16384);
#pragma unroll
    for (int ks = 0; ks < 4; ks++)
        mma_f16_ss(dA, adh + 2 * ks, bdh + 2 * ks, IDESC_N128, (!first || ks > 0) ? 1u : 0u);
#pragma unroll
    for (int ks = 0; ks < 4; ks++)
        mma_f16_ss(dA, adh + 2 * ks, bdl + 2 * ks, IDESC_N128, 1u);
#pragma unroll
    for (int ks = 0; ks < 4; ks++)
        mma_f16_ss(dA, adl + 2 * ks, bdh + 2 * ks, IDESC_N128, 1u);
}

// chunked+swizzled bf16 hi/lo epilogue store of one D tile (warps 0-3; q = row in tile)
// writer tile tau -> consumer block (tau>>1): chunk 2(q&1)+h, row 64(tau&1)+(q>>1)
__device__ __forceinline__ void epi_store_chunked(uint32_t sb, uint32_t tmem, int p,
                                                  int tau, char* consBase, int q) {
    char* blkBase = consBase + (size_t)(tau >> 1) * BLKB;
    const int il = 64 * (tau & 1) + (q >> 1);
    const int cpar = 2 * (q & 1);
#pragma unroll
    for (int qq = 0; qq < 4; qq++) {
        uint32_t d[32];
        ldtm32(d, tmem + p * 128 + qq * 32);
        wait_ld();
        char* cb = blkBase + (size_t)(cpar + (qq >> 1)) * CHB;
#pragma unroll
        for (int u = 0; u < 4; u++) {
            float4 bv0 = lds_f32x4(sb + SM_BIAS + (qq * 32 + u * 8) * 4);
            float4 bv1 = lds_f32x4(sb + SM_BIAS + (qq * 32 + u * 8 + 4) * 4);
            float4 v0, v1;
            v0.x = __uint_as_float(d[8*u+0]) + bv0.x; v0.y = __uint_as_float(d[8*u+1]) + bv0.y;
            v0.z = __uint_as_float(d[8*u+2]) + bv0.z; v0.w = __uint_as_float(d[8*u+3]) + bv0.w;
            v1.x = __uint_as_float(d[8*u+4]) + bv1.x; v1.y = __uint_as_float(d[8*u+5]) + bv1.y;
            v1.z = __uint_as_float(d[8*u+6]) + bv1.z; v1.w = __uint_as_float(d[8*u+7]) + bv1.w;
            uint4 h, l; split8(v0, v1, h, l);
            const uint32_t off = swz((uint32_t)il * 128 + (32 * (qq & 1) + 8 * u) * 2);
            *(uint4*)(cb + off) = h;
            *(uint4*)(cb + 16384 + off) = l;
        }
    }
}
#endif

// ---------------------------------------------------------------------------
__global__ void clear_flags_k() {
    int i = blockIdx.x * 256 + threadIdx.x;
    if (i < 1024) g_flags[i] = 0;
}

// ---------------------------------------------------------------------------
// Precompute: EL = emb @ W[:, :128]^T, ER = emb @ W[:, 128:]^T  (fp32 out)
// ---------------------------------------------------------------------------
__global__ __launch_bounds__(NTHREADS, 1)
void precompute_tc(const float* __restrict__ emb, const float* __restrict__ W,
                   float* __restrict__ EL, float* __restrict__ ER, int numTiles)
{
#if HAS_TCGEN05
    extern __shared__ char dsm[];
    const uint32_t sb = (smem_u32(dsm) + 1023) & ~1023u;
    const int tid = threadIdx.x, wid = tid >> 5, lid = tid & 31;

    if (tid == 0) {
#pragma unroll
        for (int s = 0; s < NSTAGE; s++) { mbar_init(SM_FULL(s) + sb, NPROD); mbar_init(SM_EMPTY(s) + sb, 1); }
#pragma unroll
        for (int p = 0; p < 2; p++) { mbar_init(SM_EPI(p) + sb, 1); mbar_init(SM_EPID(p) + sb, 128); }
    }
    {
        const int n = tid;
        const float* wrow = W + (size_t)(n & 127) * KDIM + (n >> 7) * 128;
#pragma unroll
        for (int g = 0; g < 16; g++) {
            int k0 = g * 8;
            float4 v0 = *(const float4*)(wrow + k0);
            float4 v1 = *(const float4*)(wrow + k0 + 4);
            uint4 h, l; split8(v0, v1, h, l);
            uint32_t off = (k0 >> 6) * 32768 + swz(n * 128 + (k0 & 63) * 2);
            sts128(sb + SM_B + off, h.x, h.y, h.z, h.w);
            sts128(sb + SM_BLO + off, l.x, l.y, l.z, l.w);
        }
    }
    fence_proxy_async_s();
    __syncthreads();
    if (wid == 0) { tmem_alloc(sb + SM_TMEMP, 512); tmem_relinquish(); }
    __syncthreads();
    const uint32_t tmem = (uint32_t)lds_s32(sb + SM_TMEMP);

    const bool mmaLead = (wid == 7) && elect_one();
    int uc[NSTAGE] = {0, 0, 0}, fc[NSTAGE] = {0, 0, 0}, tp[2] = {0, 0}, epc[2] = {0, 0};
    int tl = 0, prevRow = 0;

    for (int tile = blockIdx.x; tile < numTiles; tile += gridDim.x) {
        const int tileRow = tile * TILE_M;
        if (tid < NPROD) {
#pragma unroll
            for (int c = 0; c < 2; c++) {
                const int s = (tl * 2 + c) % NSTAGE;
                if (uc[s] > 0) mbar_wait(sb + SM_EMPTY(s), (uc[s] - 1) & 1);
                uc[s]++;
                const uint32_t hiB = sb + SM_A + s * 32768, loB = hiB + 16384;
                for (int i = tid; i < 1024; i += NPROD) {
                    const int row = i >> 3, oct = i & 7;
                    int er = tileRow + row; if (er > VOCAB - 1) er = VOCAB - 1;
                    const float* src = emb + (size_t)er * DDIM + c * 64 + oct * 8;
                    float4 v0 = *(const float4*)src;
                    float4 v1 = *(const float4*)(src + 4);
                    uint4 h, l; split8(v0, v1, h, l);
                    const uint32_t off = swz(row * 128 + oct * 16);
                    sts128(hiB + off, h.x, h.y, h.z, h.w);
                    sts128(loB + off, l.x, l.y, l.z, l.w);
                }
                fence_proxy_async_s();
                mbar_arrive(sb + SM_FULL(s));
            }
            if (wid < 4 && tl >= 1) {
                const int p = (tl - 1) & 1;
                mbar_wait(sb + SM_EPI(p), epc[p] & 1); epc[p]++;
                fence_after();
                const int rowg = prevRow + wid * 32 + lid;
#pragma unroll
                for (int q = 0; q < 8; q++) {
                    uint32_t d[32];
                    ldtm32(d, tmem + p * 256 + q * 32);
                    wait_ld();
                    const int col0 = q * 32;
                    float* dst = (col0 < 128 ? EL + (size_t)rowg * DDIM + col0
                                             : ER + (size_t)rowg * DDIM + (col0 - 128));
#pragma unroll
                    for (int u = 0; u < 8; u++)
                        *(float4*)(dst + u * 4) =
                            make_float4(__uint_as_float(d[4*u+0]), __uint_as_float(d[4*u+1]),
                                        __uint_as_float(d[4*u+2]), __uint_as_float(d[4*u+3]));
                }
                fence_before();
                mbar_arrive(sb + SM_EPID(p));
            }
        } else if (mmaLead) {
            const int p = tl & 1;
            if (tp[p] > 0) mbar_wait(sb + SM_EPID(p), (tp[p] - 1) & 1);
            tp[p]++;
            const uint32_t dA = tmem + p * 256;
#pragma unroll
            for (int c = 0; c < 2; c++) {
                const int s = (tl * 2 + c) % NSTAGE;
                mbar_wait(sb + SM_FULL(s), fc[s] & 1); fc[s]++;
                const uint32_t aHi = sb + SM_A + s * 32768;
                const uint64_t adh = mk_desc(aHi), adl = mk_desc(aHi + 16384);
                const uint64_t bdh = mk_desc(sb + SM_B + c * 32768);
                const uint64_t bdl = mk_desc(sb + SM_BLO + c * 32768);
#pragma unroll
                for (int ks = 0; ks < 4; ks++)
                    mma_f16_ss(dA, adh + 2 * ks, bdh + 2 * ks, IDESC_N256, (c > 0 || ks > 0) ? 1u : 0u);
#pragma unroll
                for (int ks = 0; ks < 4; ks++)
                    mma_f16_ss(dA, adh + 2 * ks, bdl + 2 * ks, IDESC_N256, 1u);
#pragma unroll
                for (int ks = 0; ks < 4; ks++)
                    mma_f16_ss(dA, adl + 2 * ks, bdh + 2 * ks, IDESC_N256, 1u);
                mma_commit(sb + SM_EMPTY(s));
            }
            mma_commit(sb + SM_EPI(p));
        }
        prevRow = tileRow; tl++;
    }

    if (wid < 4 && tl >= 1) {
        const int p = (tl - 1) & 1;
        mbar_wait(sb + SM_EPI(p), epc[p] & 1); epc[p]++;
        fence_after();
        const int rowg = prevRow + wid * 32 + lid;
#pragma unroll
        for (int q = 0; q < 8; q++) {
            uint32_t d[32];
            ldtm32(d, tmem + p * 256 + q * 32);
            wait_ld();
            const int col0 = q * 32;
            float* dst = (col0 < 128 ? EL + (size_t)rowg * DDIM + col0
                                     : ER + (size_t)rowg * DDIM + (col0 - 128));
#pragma unroll
            for (int u = 0; u < 8; u++)
                *(float4*)(dst + u * 4) =
                    make_float4(__uint_as_float(d[4*u+0]), __uint_as_float(d[4*u+1]),
                                __uint_as_float(d[4*u+2]), __uint_as_float(d[4*u+3]));
        }
        fence_before();
    }
    __syncthreads();
    if (wid == 0) tmem_dealloc(tmem, 512);
#else
    (void)emb; (void)W; (void)EL; (void)ER; (void)numTiles;
#endif
}

// ---------------------------------------------------------------------------
// Fused levels 1+2 (gather): A row m = [o(2m); o(2m+1)], o(j)=EL[ids[2j]]+ER[ids[2j+1]]+b
// Output: chunked pre-swizzled bf16 hi/lo blocks into tree arena level-0 region.
// ---------------------------------------------------------------------------
__global__ __launch_bounds__(NTHREADS, 1)
void fused12_tc(const int* __restrict__ ids,
                const float* __restrict__ EL, const float* __restrict__ ER,
                const float* __restrict__ W, const float* __restrict__ bias, int numTiles)
{
#if HAS_TCGEN05
    extern __shared__ char dsm[];
    const uint32_t sb = (smem_u32(dsm) + 1023) & ~1023u;
    const int tid = threadIdx.x, wid = tid >> 5, lid = tid & 31;
    char* arena = (char*)g_tree;

    if (tid == 0) {
#pragma unroll
        for (int s = 0; s < NSTAGE; s++) { mbar_init(SM_FULL(s) + sb, NPROD); mbar_init(SM_EMPTY(s) + sb, 1); }
#pragma unroll
        for (int p = 0; p < 2; p++) { mbar_init(SM_EPI(p) + sb, 1); mbar_init(SM_EPID(p) + sb, 128); }
    }
    if (tid < 128) sts_b32(sb + SM_BIAS + tid * 4, __float_as_uint(bias[tid]));

    {   // B = W (128 x 256) -> 4 K-chunks of 64, SW128, hi/lo
        const int n = tid >> 1, h2 = tid & 1;
#pragma unroll
        for (int g = 0; g < 16; g++) {
            int k0 = h2 * 128 + g * 8;
            float4 v0 = *(const float4*)(W + (size_t)n * KDIM + k0);
            float4 v1 = *(const float4*)(W + (size_t)n * KDIM + k0 + 4);
            uint4 h, l; split8(v0, v1, h, l);
            uint32_t off = (k0 >> 6) * 16384 + swz(n * 128 + (k0 & 63) * 2);
            sts128(sb + SM_B + off, h.x, h.y, h.z, h.w);
            sts128(sb + SM_BLO + off, l.x, l.y, l.z, l.w);
        }
    }
    fence_proxy_async_s();
    __syncthreads();
    if (wid == 0) { tmem_alloc(sb + SM_TMEMP, 256); tmem_relinquish(); }
    __syncthreads();
    const uint32_t tmem = (uint32_t)lds_s32(sb + SM_TMEMP);

    const bool mmaLead = (wid == 7) && elect_one();
    int uc[NSTAGE] = {0, 0, 0}, fc[NSTAGE] = {0, 0, 0}, tp[2] = {0, 0}, epc[2] = {0, 0};
    int tl = 0, prevTile = 0;

    for (int tile = blockIdx.x; tile < numTiles; tile += gridDim.x) {
        const int tileRow = tile * TILE_M;
        if (tid < NPROD) {
#pragma unroll
            for (int c = 0; c < 4; c++) {
                const int s = (tl * 4 + c) % NSTAGE;
                if (uc[s] > 0) mbar_wait(sb + SM_EMPTY(s), (uc[s] - 1) & 1);
                uc[s]++;
                const uint32_t hiB = sb + SM_A + s * 32768, loB = hiB + 16384;
                for (int i = tid; i < 1024; i += NPROD) {
                    const int row = i >> 3, oct = i & 7;
                    const int j = 2 * (tileRow + row) + (c >> 1);
                    const int idL = ids[2 * j], idR = ids[2 * j + 1];
                    const int sub = (c & 1) * 64 + oct * 8;
                    const float* pl = EL + (size_t)idL * DDIM + sub;
                    const float* pr = ER + (size_t)idR * DDIM + sub;
                    float4 l0 = *(const float4*)pl,       r0 = *(const float4*)pr;
                    float4 l1 = *(const float4*)(pl + 4), r1 = *(const float4*)(pr + 4);
                    float4 b0 = lds_f32x4(sb + SM_BIAS + sub * 4);
                    float4 b1 = lds_f32x4(sb + SM_BIAS + (sub + 4) * 4);
                    float4 v0, v1;
                    v0.x = l0.x + r0.x + b0.x; v0.y = l0.y + r0.y + b0.y;
                    v0.z = l0.z + r0.z + b0.z; v0.w = l0.w + r0.w + b0.w;
                    v1.x = l1.x + r1.x + b1.x; v1.y = l1.y + r1.y + b1.y;
                    v1.z = l1.z + r1.z + b1.z; v1.w = l1.w + r1.w + b1.w;
                    uint4 h, l; split8(v0, v1, h, l);
                    const uint32_t off = swz(row * 128 + oct * 16);
                    sts128(hiB + off, h.x, h.y, h.z, h.w);
                    sts128(loB + off, l.x, l.y, l.z, l.w);
                }
                fence_proxy_async_s();
                mbar_arrive(sb + SM_FULL(s));
            }
            if (wid < 4 && tl >= 1) {
                const int p = (tl - 1) & 1;
                mbar_wait(sb + SM_EPI(p), epc[p] & 1); epc[p]++;
                fence_after();
                epi_store_chunked(sb, tmem, p, prevTile, arena, wid * 32 + lid);
                fence_before();
                mbar_arrive(sb + SM_EPID(p));
            }
        } else if (mmaLead) {
            const int p = tl & 1;
            if (tp[p] > 0) mbar_wait(sb + SM_EPID(p), (tp[p] - 1) & 1);
            tp[p]++;
            const uint32_t dA = tmem + p * 128;
#pragma unroll
            for (int c = 0; c < 4; c++) {
                const int s = (tl * 4 + c) % NSTAGE;
                mbar_wait(sb + SM_FULL(s), fc[s] & 1); fc[s]++;
                mma_chunk(dA, sb, s, c, c == 0);
                mma_commit(sb + SM_EMPTY(s));
            }
            mma_commit(sb + SM_EPI(p));
        }
        prevTile = tile; tl++;
    }

    if (wid < 4 && tl >= 1) {
        const int p = (tl - 1) & 1;
        mbar_wait(sb + SM_EPI(p), epc[p] & 1); epc[p]++;
        fence_after();
        epi_store_chunked(sb, tmem, p, prevTile, arena, wid * 32 + lid);
        fence_before();
    }
    __syncthreads();
    if (wid == 0) tmem_dealloc(tmem, 256);
#else
    (void)ids; (void)EL; (void)ER; (void)W; (void)bias; (void)numTiles;
#endif
}

// ---------------------------------------------------------------------------
// Persistent tree kernel: all 9 remaining levels (1022 tiles), flag-ordered.
// A tiles arrive via cp.async.bulk from pre-split chunked blocks; zero producer warps.
// ---------------------------------------------------------------------------
__global__ __launch_bounds__(NTHREADS, 1)
void tree_tc(const float* __restrict__ W, const float* __restrict__ bias,
             float* __restrict__ out)
{
#if HAS_TCGEN05
    extern __shared__ char dsm[];
    const uint32_t sb = (smem_u32(dsm) + 1023) & ~1023u;
    const int tid = threadIdx.x, wid = tid >> 5, lid = tid & 31;
    char* arena = (char*)g_tree;

    if (tid == 0) {
#pragma unroll
        for (int s = 0; s < NSTAGE; s++) { mbar_init(SM_FULL(s) + sb, 1); mbar_init(SM_EMPTY(s) + sb, 1); }
#pragma unroll
        for (int p = 0; p < 2; p++) { mbar_init(SM_EPI(p) + sb, 1); mbar_init(SM_EPID(p) + sb, 4); }
    }
    if (tid < 128) sts_b32(sb + SM_BIAS + tid * 4, __float_as_uint(bias[tid]));

    {   // B = W chunks (same layout as fused12)
        const int n = tid >> 1, h2 = tid & 1;
#pragma unroll
        for (int g = 0; g < 16; g++) {
            int k0 = h2 * 128 + g * 8;
            float4 v0 = *(const float4*)(W + (size_t)n * KDIM + k0);
            float4 v1 = *(const float4*)(W + (size_t)n * KDIM + k0 + 4);
            uint4 h, l; split8(v0, v1, h, l);
            uint32_t off = (k0 >> 6) * 16384 + swz(n * 128 + (k0 & 63) * 2);
            sts128(sb + SM_B + off, h.x, h.y, h.z, h.w);
            sts128(sb + SM_BLO + off, l.x, l.y, l.z, l.w);
        }
    }
    fence_proxy_async_s();
    __syncthreads();
    if (wid == 0) { tmem_alloc(sb + SM_TMEMP, 256); tmem_relinquish(); }
    __syncthreads();
    const uint32_t tmem = (uint32_t)lds_s32(sb + SM_TMEMP);

    const bool isu = (wid == 7) && elect_one();
    int issued[NSTAGE] = {0, 0, 0}, fc[NSTAGE] = {0, 0, 0}, tp[2] = {0, 0}, epc[2] = {0, 0};
    int tl = 0, prevL = 0, prevT = 0;
    bool havePrev = false;

    for (int g = blockIdx.x; g < NTREE; g += gridDim.x) {
        int L = 0;
        while (g >= c_off[L + 1]) L++;
        const int t = g - c_off[L];
        const char* inP = arena + (size_t)g * BLKB;   // input block index == global id

        if (isu) {
            if (L > 0) {   // wait both dependency tiles (128 epilogue-thread arrivals each)
                int* f0 = &g_flags[c_off[L - 1] + 2 * t];
                while (ld_acq(f0) < 128 || ld_acq(f0 + 1) < 128) nsleep();
            }
            // issue chunks 0..2 into the 3-stage ring
#pragma unroll
            for (int c = 0; c < 3; c++) {
                const int s = (tl * 4 + c) % NSTAGE;
                if (issued[s] > 0) mbar_wait(sb + SM_EMPTY(s), (issued[s] - 1) & 1);
                issued[s]++;
                mbar_expect_tx(sb + SM_FULL(s), 32768);
                bulk_g2s(sb + SM_A + s * 32768,         inP + c * CHB,         16384, sb + SM_FULL(s));
                bulk_g2s(sb + SM_A + s * 32768 + 16384, inP + c * CHB + 16384, 16384, sb + SM_FULL(s));
            }
            const int p = tl & 1;
            if (tp[p] > 0) mbar_wait(sb + SM_EPID(p), (tp[p] - 1) & 1);
            tp[p]++;
            const uint32_t dA = tmem + p * 128;
            // consume chunk 0
            {
                const int s = (tl * 4) % NSTAGE;
                mbar_wait(sb + SM_FULL(s), fc[s] & 1); fc[s]++;
                mma_chunk(dA, sb, s, 0, true);
                mma_commit(sb + SM_EMPTY(s));
            }
            // issue chunk 3 (reuses chunk-0 stage after its MMA retires)
            {
                const int s = (tl * 4 + 3) % NSTAGE;
                mbar_wait(sb + SM_EMPTY(s), (issued[s] - 1) & 1);
                issued[s]++;
                mbar_expect_tx(sb + SM_FULL(s), 32768);
                bulk_g2s(sb + SM_A + s * 32768,         inP + 3 * CHB,         16384, sb + SM_FULL(s));
                bulk_g2s(sb + SM_A + s * 32768 + 16384, inP + 3 * CHB + 16384, 16384, sb + SM_FULL(s));
            }
            // consume chunks 1..3
#pragma unroll
            for (int c = 1; c < 4; c++) {
                const int s = (tl * 4 + c) % NSTAGE;
                mbar_wait(sb + SM_FULL(s), fc[s] & 1); fc[s]++;
                mma_chunk(dA, sb, s, c, false);
                mma_commit(sb + SM_EMPTY(s));
            }
            mma_commit(sb + SM_EPI(p));
        }

        if (wid < 4 && havePrev) {
            const int p = (tl - 1) & 1;
            mbar_wait(sb + SM_EPI(p), epc[p] & 1); epc[p]++;
            fence_after();
            const int q = wid * 32 + lid;
            if (prevL == 8) {
                float* op = out + (size_t)(128 * prevT + q) * DDIM;
#pragma unroll
                for (int qq = 0; qq < 4; qq++) {
                    uint32_t d[32];
                    ldtm32(d, tmem + p * 128 + qq * 32);
                    wait_ld();
#pragma unroll
                    for (int u = 0; u < 8; u++) {
                        float4 bv = lds_f32x4(sb + SM_BIAS + (qq * 32 + u * 4) * 4);
                        *(float4*)(op + qq * 32 + u * 4) =
                            make_float4(__uint_as_float(d[4*u+0]) + bv.x, __uint_as_float(d[4*u+1]) + bv.y,
                                        __uint_as_float(d[4*u+2]) + bv.z, __uint_as_float(d[4*u+3]) + bv.w);
                    }
                }
            } else {
                epi_store_chunked(sb, tmem, p, prevT, arena + (size_t)c_off[prevL + 1] * BLKB, q);
                red_rel_add1(&g_flags[c_off[prevL] + prevT]);   // per-thread release arrival (128 total)
            }
            fence_before();
            __syncwarp();
            if (lid == 0) mbar_arrive(sb + SM_EPID(p));
        }
        prevL = L; prevT = t; havePrev = true; tl++;
    }

    if (wid < 4 && havePrev) {   // drain last tile
        const int p = (tl - 1) & 1;
        mbar_wait(sb + SM_EPI(p), epc[p] & 1); epc[p]++;
        fence_after();
        const int q = wid * 32 + lid;
        if (prevL == 8) {
            float* op = out + (size_t)(128 * prevT + q) * DDIM;
#pragma unroll
            for (int qq = 0; qq < 4; qq++) {
                uint32_t d[32];
                ldtm32(d, tmem + p * 128 + qq * 32);
                wait_ld();
#pragma unroll
                for (int u = 0; u < 8; u++) {
                    float4 bv = lds_f32x4(sb + SM_BIAS + (qq * 32 + u * 4) * 4);
                    *(float4*)(op + qq * 32 + u * 4) =
                        make_float4(__uint_as_float(d[4*u+0]) + bv.x, __uint_as_float(d[4*u+1]) + bv.y,
                                    __uint_as_float(d[4*u+2]) + bv.z, __uint_as_float(d[4*u+3]) + bv.w);
                }
            }
        } else {
            epi_store_chunked(sb, tmem, p, prevT, arena + (size_t)c_off[prevL + 1] * BLKB, q);
            red_rel_add1(&g_flags[c_off[prevL] + prevT]);
        }
        fence_before();
    }
    __syncthreads();
    if (wid == 0) tmem_dealloc(tmem, 256);
#else
    (void)W; (void)bias; (void)out;
#endif
}

// ---------------------------------------------------------------------------
extern "C" void kernel_launch(void* const* d_in, const int* in_sizes, int n_in,
                              void* d_out, int out_size)
{
    (void)in_sizes; (void)n_in; (void)out_size;
    const int*   ids  = (const int*)d_in[0];
    const float* emb  = (const float*)d_in[1];
    const float* W    = (const float*)d_in[2];
    const float* bias = (const float*)d_in[3];
    float* out = (float*)d_out;

    static bool attr_set = false;
    if (!attr_set) {
        cudaFuncSetAttribute(precompute_tc, cudaFuncAttributeMaxDynamicSharedMemorySize, DYN_SMEM);
        cudaFuncSetAttribute(fused12_tc,    cudaFuncAttributeMaxDynamicSharedMemorySize, DYN_SMEM);
        cudaFuncSetAttribute(tree_tc,       cudaFuncAttributeMaxDynamicSharedMemorySize, DYN_SMEM);
        attr_set = true;
    }

    float *elp, *erp;
    cudaGetSymbolAddress((void**)&elp, g_EL);
    cudaGetSymbolAddress((void**)&erp, g_ER);

    clear_flags_k<<<4, 256>>>();
    precompute_tc<<<148, NTHREADS, DYN_SMEM>>>(emb, W, elp, erp, VOCABPAD / TILE_M);
    fused12_tc<<<148, NTHREADS, DYN_SMEM>>>(ids, elp, erp, W, bias, 1024);
    tree_tc<<<148, NTHREADS, DYN_SMEM>>>(W, bias, out);
}

// round 7
// speedup vs baseline: 3.2650x; 1.0690x over previous
#include <cuda_runtime.h>
#include <cstdint>

#define VOCAB    100000
#define VOCABPAD 100096
#define DDIM     128
#define KDIM     256
#define NTHREADS 256
#define NPROD    224
#define TILE_M   128
#define NSTAGE   3

#define NTREE    1022                   // 512+256+128+64+32+16+8+4+2
#define BLKB     131072u                // bytes per consumer-tile block (4 chunks x (hi+lo) 16KB)
#define CHB      32768u                 // bytes per chunk (hi 16KB + lo 16KB)

#if !defined(__CUDA_ARCH__) || defined(__CUDA_ARCH_FEAT_SM103_ALL) || \
    (defined(__CUDA_ARCH_SPECIFIC__) && (__CUDA_ARCH_SPECIFIC__ == 1030))
#define HAS_TCGEN05 1
#else
#define HAS_TCGEN05 0
#endif

// ---- SMEM frame (offsets from 1KB-aligned base) ----
#define SM_B     0                      // 4 chunks x 16KB hi  | pre: 2 x 32KB
#define SM_BLO   65536                  // lo mirror
#define SM_A     131072                 // 3 stages x 32KB (hi 16KB + lo 16KB)
#define SM_HDR   229376
#define SM_TMEMP (SM_HDR + 0)
#define SM_FULL(s)  (SM_HDR + 16 + (s) * 8)
#define SM_EMPTY(s) (SM_HDR + 48 + (s) * 8)
#define SM_EPI(p)   (SM_HDR + 80 + (p) * 8)
#define SM_EPID(p)  (SM_HDR + 96 + (p) * 8)
#define SM_BIAS  (SM_HDR + 128)
#define DYN_SMEM 231424

#define IDESC_N128 0x8200490u
#define IDESC_N256 0x8400490u

// level tile-count prefix sums (global tile ids, level-major)
__constant__ int c_off[10] = {0, 512, 768, 896, 960, 992, 1008, 1016, 1020, 1022};

// ---- device scratch ----
__device__ uint4 g_tree[NTREE * BLKB / 16];      // 134MB arena of chunked bf16 hi/lo blocks
__device__ int   g_flags[1024];
__device__ float g_EL[VOCABPAD * 128];
__device__ float g_ER[VOCABPAD * 128];

// ---------------- PTX helpers ----------------
__device__ __forceinline__ uint32_t smem_u32(const void* p) {
    uint32_t a;
    asm("{ .reg .u64 t; cvta.to.shared.u64 t, %1; cvt.u32.u64 %0, t; }" : "=r"(a) : "l"(p));
    return a;
}
__device__ __forceinline__ bool elect_one() {
    uint32_t pred;
    asm volatile("{ .reg .pred p; elect.sync _|p, 0xFFFFFFFF; selp.b32 %0, 1, 0, p; }" : "=r"(pred));
    return pred != 0;
}
__device__ __forceinline__ void sts128(uint32_t a, uint32_t x, uint32_t y, uint32_t z, uint32_t w) {
    asm volatile("st.shared.v4.b32 [%0], {%1,%2,%3,%4};" :: "r"(a), "r"(x), "r"(y), "r"(z), "r"(w) : "memory");
}
__device__ __forceinline__ int lds_s32(uint32_t a) {
    int v; asm volatile("ld.shared.b32 %0, [%1];" : "=r"(v) : "r"(a)); return v;
}
__device__ __forceinline__ float4 lds_f32x4(uint32_t a) {
    float4 v;
    asm volatile("ld.shared.v4.f32 {%0,%1,%2,%3}, [%4];"
                 : "=f"(v.x), "=f"(v.y), "=f"(v.z), "=f"(v.w) : "r"(a));
    return v;
}
__device__ __forceinline__ void sts_b32(uint32_t a, uint32_t v) {
    asm volatile("st.shared.b32 [%0], %1;" :: "r"(a), "r"(v) : "memory");
}
__device__ __forceinline__ void mbar_init(uint32_t a, uint32_t c) {
    asm volatile("mbarrier.init.shared.b64 [%0], %1;" :: "r"(a), "r"(c) : "memory");
}
__device__ __forceinline__ void mbar_arrive(uint32_t a) {
    asm volatile("mbarrier.arrive.shared.b64 _, [%0];" :: "r"(a) : "memory");
}
__device__ __forceinline__ void mbar_expect_tx(uint32_t a, uint32_t bytes) {
    asm volatile("mbarrier.arrive.expect_tx.shared.b64 _, [%0], %1;" :: "r"(a), "r"(bytes) : "memory");
}
__device__ __forceinline__ void bulk_g2s(uint32_t dst, const char* src, uint32_t bytes, uint32_t mbar) {
    asm volatile("cp.async.bulk.shared::cluster.global.mbarrier::complete_tx::bytes [%0], [%1], %2, [%3];"
                 :: "r"(dst), "l"(src), "r"(bytes), "r"(mbar) : "memory");
}
__device__ __forceinline__ void fence_proxy_async_s() {
    asm volatile("fence.proxy.async.shared::cta;" ::: "memory");
}
__device__ __forceinline__ int ld_acq(const int* p) {
    int v; asm volatile("ld.acquire.gpu.global.b32 %0, [%1];" : "=r"(v) : "l"(p) : "memory");
    return v;
}
__device__ __forceinline__ void red_rel_add1(int* p) {
    asm volatile("red.release.gpu.global.add.s32 [%0], 1;" :: "l"(p) : "memory");
}
__device__ __forceinline__ void nsleep() { asm volatile("nanosleep.u32 64;" ::: ); }

#if HAS_TCGEN05
__device__ __forceinline__ void mbar_wait(uint32_t a, uint32_t parity) {
    asm volatile(
        "{\n\t.reg .pred P;\n\t"
        "W%=:\n\t"
        "mbarrier.try_wait.parity.acquire.cta.shared::cta.b64 P, [%0], %1, 0x989680;\n\t"
        "@P bra.uni D%=;\n\t"
        "bra.uni W%=;\n\t"
        "D%=:\n\t}"
        :: "r"(a), "r"(parity) : "memory");
}
__device__ __forceinline__ void tmem_alloc(uint32_t dst, uint32_t n) {
    asm volatile("tcgen05.alloc.cta_group::1.sync.aligned.shared::cta.b32 [%0], %1;"
                 :: "r"(dst), "r"(n) : "memory");
}
__device__ __forceinline__ void tmem_relinquish() {
    asm volatile("tcgen05.relinquish_alloc_permit.cta_group::1.sync.aligned;");
}
__device__ __forceinline__ void tmem_dealloc(uint32_t t, uint32_t n) {
    asm volatile("tcgen05.dealloc.cta_group::1.sync.aligned.b32 %0, %1;" :: "r"(t), "r"(n));
}
__device__ __forceinline__ void mma_f16_ss(uint32_t d, uint64_t ad, uint64_t bd, uint32_t idesc, uint32_t en) {
    asm volatile(
        "{\n\t.reg .pred p;\n\tsetp.ne.u32 p, %4, 0;\n\t"
        "tcgen05.mma.cta_group::1.kind::f16 [%0], %1, %2, %3, {%5,%5,%5,%5}, p;\n\t}"
        :: "r"(d), "l"(ad), "l"(bd), "r"(idesc), "r"(en), "r"(0u) : "memory");
}
__device__ __forceinline__ void mma_commit(uint32_t mbar) {
    asm volatile("tcgen05.commit.cta_group::1.mbarrier::arrive::one.shared::cluster.b64 [%0];"
                 :: "r"(mbar) : "memory");
}
__device__ __forceinline__ void fence_after()  { asm volatile("tcgen05.fence::after_thread_sync;"  ::: "memory"); }
__device__ __forceinline__ void fence_before() { asm volatile("tcgen05.fence::before_thread_sync;" ::: "memory"); }
__device__ __forceinline__ void wait_ld()      { asm volatile("tcgen05.wait::ld.sync.aligned;"     ::: "memory"); }
__device__ __forceinline__ void ldtm32(uint32_t* r, uint32_t ta) {
    asm volatile(
        "tcgen05.ld.sync.aligned.32x32b.x32.b32 "
        "{%0, %1, %2, %3, %4, %5, %6, %7, "
        " %8, %9, %10, %11, %12, %13, %14, %15, "
        " %16, %17, %18, %19, %20, %21, %22, %23, "
        " %24, %25, %26, %27, %28, %29, %30, %31}, [%32];"
        : "=r"(r[0]), "=r"(r[1]), "=r"(r[2]), "=r"(r[3]),
          "=r"(r[4]), "=r"(r[5]), "=r"(r[6]), "=r"(r[7]),
          "=r"(r[8]), "=r"(r[9]), "=r"(r[10]), "=r"(r[11]),
          "=r"(r[12]), "=r"(r[13]), "=r"(r[14]), "=r"(r[15]),
          "=r"(r[16]), "=r"(r[17]), "=r"(r[18]), "=r"(r[19]),
          "=r"(r[20]), "=r"(r[21]), "=r"(r[22]), "=r"(r[23]),
          "=r"(r[24]), "=r"(r[25]), "=r"(r[26]), "=r"(r[27]),
          "=r"(r[28]), "=r"(r[29]), "=r"(r[30]), "=r"(r[31])
        : "r"(ta));
}
#endif // HAS_TCGEN05

__device__ __forceinline__ uint32_t swz(uint32_t off) { return off ^ ((off >> 3) & 0x70); }

__device__ __forceinline__ uint64_t mk_desc(uint32_t addr) {
    const uint64_t base = (uint64_t(2) << 61) | (uint64_t(1) << 46) |
                          (uint64_t(64) << 32) | (uint64_t(1) << 16);
    return base | ((uint64_t)(addr >> 4) & 0x3FFF);
}

// split 8 fp32 -> bf16 hi + exact-residual bf16 lo
__device__ __forceinline__ void split8(const float4& v0, const float4& v1, uint4& h, uint4& l) {
    float f[8] = {v0.x, v0.y, v0.z, v0.w, v1.x, v1.y, v1.z, v1.w};
    uint32_t hh[4], ll[4];
#pragma unroll
    for (int q = 0; q < 4; q++) {
        float a = f[2 * q], b = f[2 * q + 1];
        uint32_t hv;
        asm("cvt.rn.bf16x2.f32 %0, %1, %2;" : "=r"(hv) : "f"(b), "f"(a));
        hh[q] = hv;
        float ha = __uint_as_float(hv << 16);
        float hb = __uint_as_float(hv & 0xFFFF0000u);
        asm("cvt.rn.bf16x2.f32 %0, %1, %2;" : "=r"(ll[q]) : "f"(b - hb), "f"(a - ha));
    }
    h = make_uint4(hh[0], hh[1], hh[2], hh[3]);
    l = make_uint4(ll[0], ll[1], ll[2], ll[3]);
}

#if HAS_TCGEN05
// 12 split-MMAs for one K=64 chunk (A in stage s, B chunk c); first: fresh accumulate
__device__ __forceinline__ void mma_chunk(uint32_t dA, uint32_t sb, int s, int c, bool first) {
    const uint32_t aHi = sb + SM_A + s * 32768;
    const uint64_t adh = mk_desc(aHi), adl = mk_desc(aHi + 16384);
    const uint64_t bdh = mk_desc(sb + SM_B + c * 16384);
    const uint64_t bdl = mk_desc(sb + SM_BLO + c * 16384);
#pragma unroll
    for (int ks = 0; ks < 4; ks++)
        mma_f16_ss(dA, adh + 2 * ks, bdh + 2 * ks, IDESC_N128, (!first || ks > 0) ? 1u : 0u);
#pragma unroll
    for (int ks = 0; ks < 4; ks++)
        mma_f16_ss(dA, adh + 2 * ks, bdl + 2 * ks, IDESC_N128, 1u);
#pragma unroll
    for (int ks = 0; ks < 4; ks++)
        mma_f16_ss(dA, adl + 2 * ks, bdh + 2 * ks, IDESC_N128, 1u);
}

// chunked+swizzled bf16 hi/lo epilogue store of one D tile (warps 0-3; q = row in tile)
__device__ __forceinline__ void epi_store_chunked(uint32_t sb, uint32_t tmem, int p,
                                                  int tau, char* consBase, int q) {
    char* blkBase = consBase + (size_t)(tau >> 1) * BLKB;
    const int il = 64 * (tau & 1) + (q >> 1);
    const int cpar = 2 * (q & 1);
#pragma unroll
    for (int qq = 0; qq < 4; qq++) {
        uint32_t d[32];
        ldtm32(d, tmem + p * 128 + qq * 32);
        wait_ld();
        char* cb = blkBase + (size_t)(cpar + (qq >> 1)) * CHB;
#pragma unroll
        for (int u = 0; u < 4; u++) {
            float4 bv0 = lds_f32x4(sb + SM_BIAS + (qq * 32 + u * 8) * 4);
            float4 bv1 = lds_f32x4(sb + SM_BIAS + (qq * 32 + u * 8 + 4) * 4);
            float4 v0, v1;
            v0.x = __uint_as_float(d[8*u+0]) + bv0.x; v0.y = __uint_as_float(d[8*u+1]) + bv0.y;
            v0.z = __uint_as_float(d[8*u+2]) + bv0.z; v0.w = __uint_as_float(d[8*u+3]) + bv0.w;
            v1.x = __uint_as_float(d[8*u+4]) + bv1.x; v1.y = __uint_as_float(d[8*u+5]) + bv1.y;
            v1.z = __uint_as_float(d[8*u+6]) + bv1.z; v1.w = __uint_as_float(d[8*u+7]) + bv1.w;
            uint4 h, l; split8(v0, v1, h, l);
            const uint32_t off = swz((uint32_t)il * 128 + (32 * (qq & 1) + 8 * u) * 2);
            *(uint4*)(cb + off) = h;
            *(uint4*)(cb + 16384 + off) = l;
        }
    }
}
#endif

// ---------------------------------------------------------------------------
__global__ void clear_flags_k() {
    int i = blockIdx.x * 256 + threadIdx.x;
    if (i < 1024) g_flags[i] = 0;
}

// ---------------------------------------------------------------------------
// Precompute: EL = emb @ W[:, :128]^T, ER = emb @ W[:, 128:]^T  (fp32 out)
// ---------------------------------------------------------------------------
__global__ __launch_bounds__(NTHREADS, 1)
void precompute_tc(const float* __restrict__ emb, const float* __restrict__ W,
                   float* __restrict__ EL, float* __restrict__ ER, int numTiles)
{
#if HAS_TCGEN05
    extern __shared__ char dsm[];
    const uint32_t sb = (smem_u32(dsm) + 1023) & ~1023u;
    const int tid = threadIdx.x, wid = tid >> 5, lid = tid & 31;

    if (tid == 0) {
#pragma unroll
        for (int s = 0; s < NSTAGE; s++) { mbar_init(SM_FULL(s) + sb, NPROD); mbar_init(SM_EMPTY(s) + sb, 1); }
#pragma unroll
        for (int p = 0; p < 2; p++) { mbar_init(SM_EPI(p) + sb, 1); mbar_init(SM_EPID(p) + sb, 128); }
    }
    {
        const int n = tid;
        const float* wrow = W + (size_t)(n & 127) * KDIM + (n >> 7) * 128;
#pragma unroll
        for (int g = 0; g < 16; g++) {
            int k0 = g * 8;
            float4 v0 = *(const float4*)(wrow + k0);
            float4 v1 = *(const float4*)(wrow + k0 + 4);
            uint4 h, l; split8(v0, v1, h, l);
            uint32_t off = (k0 >> 6) * 32768 + swz(n * 128 + (k0 & 63) * 2);
            sts128(sb + SM_B + off, h.x, h.y, h.z, h.w);
            sts128(sb + SM_BLO + off, l.x, l.y, l.z, l.w);
        }
    }
    fence_proxy_async_s();
    __syncthreads();
    if (wid == 0) { tmem_alloc(sb + SM_TMEMP, 512); tmem_relinquish(); }
    __syncthreads();
    const uint32_t tmem = (uint32_t)lds_s32(sb + SM_TMEMP);

    const bool mmaLead = (wid == 7) && elect_one();
    int uc[NSTAGE] = {0, 0, 0}, fc[NSTAGE] = {0, 0, 0}, tp[2] = {0, 0}, epc[2] = {0, 0};
    int tl = 0, prevRow = 0;

    for (int tile = blockIdx.x; tile < numTiles; tile += gridDim.x) {
        const int tileRow = tile * TILE_M;
        if (tid < NPROD) {
#pragma unroll
            for (int c = 0; c < 2; c++) {
                const int s = (tl * 2 + c) % NSTAGE;
                if (uc[s] > 0) mbar_wait(sb + SM_EMPTY(s), (uc[s] - 1) & 1);
                uc[s]++;
                const uint32_t hiB = sb + SM_A + s * 32768, loB = hiB + 16384;
                for (int i = tid; i < 1024; i += NPROD) {
                    const int row = i >> 3, oct = i & 7;
                    int er = tileRow + row; if (er > VOCAB - 1) er = VOCAB - 1;
                    const float* src = emb + (size_t)er * DDIM + c * 64 + oct * 8;
                    float4 v0 = *(const float4*)src;
                    float4 v1 = *(const float4*)(src + 4);
                    uint4 h, l; split8(v0, v1, h, l);
                    const uint32_t off = swz(row * 128 + oct * 16);
                    sts128(hiB + off, h.x, h.y, h.z, h.w);
                    sts128(loB + off, l.x, l.y, l.z, l.w);
                }
                fence_proxy_async_s();
                mbar_arrive(sb + SM_FULL(s));
            }
            if (wid < 4 && tl >= 1) {
                const int p = (tl - 1) & 1;
                mbar_wait(sb + SM_EPI(p), epc[p] & 1); epc[p]++;
                fence_after();
                const int rowg = prevRow + wid * 32 + lid;
#pragma unroll
                for (int q = 0; q < 8; q++) {
                    uint32_t d[32];
                    ldtm32(d, tmem + p * 256 + q * 32);
                    wait_ld();
                    const int col0 = q * 32;
                    float* dst = (col0 < 128 ? EL + (size_t)rowg * DDIM + col0
                                             : ER + (size_t)rowg * DDIM + (col0 - 128));
#pragma unroll
                    for (int u = 0; u < 8; u++)
                        *(float4*)(dst + u * 4) =
                            make_float4(__uint_as_float(d[4*u+0]), __uint_as_float(d[4*u+1]),
                                        __uint_as_float(d[4*u+2]), __uint_as_float(d[4*u+3]));
                }
                fence_before();
                mbar_arrive(sb + SM_EPID(p));
            }
        } else if (mmaLead) {
            const int p = tl & 1;
            if (tp[p] > 0) mbar_wait(sb + SM_EPID(p), (tp[p] - 1) & 1);
            tp[p]++;
            const uint32_t dA = tmem + p * 256;
#pragma unroll
            for (int c = 0; c < 2; c++) {
                const int s = (tl * 2 + c) % NSTAGE;
                mbar_wait(sb + SM_FULL(s), fc[s] & 1); fc[s]++;
                const uint32_t aHi = sb + SM_A + s * 32768;
                const uint64_t adh = mk_desc(aHi), adl = mk_desc(aHi + 16384);
                const uint64_t bdh = mk_desc(sb + SM_B + c * 32768);
                const uint64_t bdl = mk_desc(sb + SM_BLO + c * 32768);
#pragma unroll
                for (int ks = 0; ks < 4; ks++)
                    mma_f16_ss(dA, adh + 2 * ks, bdh + 2 * ks, IDESC_N256, (c > 0 || ks > 0) ? 1u : 0u);
#pragma unroll
                for (int ks = 0; ks < 4; ks++)
                    mma_f16_ss(dA, adh + 2 * ks, bdl + 2 * ks, IDESC_N256, 1u);
#pragma unroll
                for (int ks = 0; ks < 4; ks++)
                    mma_f16_ss(dA, adl + 2 * ks, bdh + 2 * ks, IDESC_N256, 1u);
                mma_commit(sb + SM_EMPTY(s));
            }
            mma_commit(sb + SM_EPI(p));
        }
        prevRow = tileRow; tl++;
    }

    if (wid < 4 && tl >= 1) {
        const int p = (tl - 1) & 1;
        mbar_wait(sb + SM_EPI(p), epc[p] & 1); epc[p]++;
        fence_after();
        const int rowg = prevRow + wid * 32 + lid;
#pragma unroll
        for (int q = 0; q < 8; q++) {
            uint32_t d[32];
            ldtm32(d, tmem + p * 256 + q * 32);
            wait_ld();
            const int col0 = q * 32;
            float* dst = (col0 < 128 ? EL + (size_t)rowg * DDIM + col0
                                     : ER + (size_t)rowg * DDIM + (col0 - 128));
#pragma unroll
            for (int u = 0; u < 8; u++)
                *(float4*)(dst + u * 4) =
                    make_float4(__uint_as_float(d[4*u+0]), __uint_as_float(d[4*u+1]),
                                __uint_as_float(d[4*u+2]), __uint_as_float(d[4*u+3]));
        }
        fence_before();
    }
    __syncthreads();
    if (wid == 0) tmem_dealloc(tmem, 512);
#else
    (void)emb; (void)W; (void)EL; (void)ER; (void)numTiles;
#endif
}

// ---------------------------------------------------------------------------
// Fused levels 1+2 (gather) -> chunked pre-swizzled bf16 hi/lo blocks (arena L0)
// ---------------------------------------------------------------------------
__global__ __launch_bounds__(NTHREADS, 1)
void fused12_tc(const int* __restrict__ ids,
                const float* __restrict__ EL, const float* __restrict__ ER,
                const float* __restrict__ W, const float* __restrict__ bias, int numTiles)
{
#if HAS_TCGEN05
    extern __shared__ char dsm[];
    const uint32_t sb = (smem_u32(dsm) + 1023) & ~1023u;
    const int tid = threadIdx.x, wid = tid >> 5, lid = tid & 31;
    char* arena = (char*)g_tree;

    if (tid == 0) {
#pragma unroll
        for (int s = 0; s < NSTAGE; s++) { mbar_init(SM_FULL(s) + sb, NPROD); mbar_init(SM_EMPTY(s) + sb, 1); }
#pragma unroll
        for (int p = 0; p < 2; p++) { mbar_init(SM_EPI(p) + sb, 1); mbar_init(SM_EPID(p) + sb, 128); }
    }
    if (tid < 128) sts_b32(sb + SM_BIAS + tid * 4, __float_as_uint(bias[tid]));

    {   // B = W (128 x 256) -> 4 K-chunks of 64, SW128, hi/lo
        const int n = tid >> 1, h2 = tid & 1;
#pragma unroll
        for (int g = 0; g < 16; g++) {
            int k0 = h2 * 128 + g * 8;
            float4 v0 = *(const float4*)(W + (size_t)n * KDIM + k0);
            float4 v1 = *(const float4*)(W + (size_t)n * KDIM + k0 + 4);
            uint4 h, l; split8(v0, v1, h, l);
            uint32_t off = (k0 >> 6) * 16384 + swz(n * 128 + (k0 & 63) * 2);
            sts128(sb + SM_B + off, h.x, h.y, h.z, h.w);
            sts128(sb + SM_BLO + off, l.x, l.y, l.z, l.w);
        }
    }
    fence_proxy_async_s();
    __syncthreads();
    if (wid == 0) { tmem_alloc(sb + SM_TMEMP, 256); tmem_relinquish(); }
    __syncthreads();
    const uint32_t tmem = (uint32_t)lds_s32(sb + SM_TMEMP);

    const bool mmaLead = (wid == 7) && elect_one();
    int uc[NSTAGE] = {0, 0, 0}, fc[NSTAGE] = {0, 0, 0}, tp[2] = {0, 0}, epc[2] = {0, 0};
    int tl = 0, prevTile = 0;

    for (int tile = blockIdx.x; tile < numTiles; tile += gridDim.x) {
        const int tileRow = tile * TILE_M;
        if (tid < NPROD) {
#pragma unroll
            for (int c = 0; c < 4; c++) {
                const int s = (tl * 4 + c) % NSTAGE;
                if (uc[s] > 0) mbar_wait(sb + SM_EMPTY(s), (uc[s] - 1) & 1);
                uc[s]++;
                const uint32_t hiB = sb + SM_A + s * 32768, loB = hiB + 16384;
                for (int i = tid; i < 1024; i += NPROD) {
                    const int row = i >> 3, oct = i & 7;
                    const int j = 2 * (tileRow + row) + (c >> 1);
                    const int idL = ids[2 * j], idR = ids[2 * j + 1];
                    const int sub = (c & 1) * 64 + oct * 8;
                    const float* pl = EL + (size_t)idL * DDIM + sub;
                    const float* pr = ER + (size_t)idR * DDIM + sub;
                    float4 l0 = *(const float4*)pl,       r0 = *(const float4*)pr;
                    float4 l1 = *(const float4*)(pl + 4), r1 = *(const float4*)(pr + 4);
                    float4 b0 = lds_f32x4(sb + SM_BIAS + sub * 4);
                    float4 b1 = lds_f32x4(sb + SM_BIAS + (sub + 4) * 4);
                    float4 v0, v1;
                    v0.x = l0.x + r0.x + b0.x; v0.y = l0.y + r0.y + b0.y;
                    v0.z = l0.z + r0.z + b0.z; v0.w = l0.w + r0.w + b0.w;
                    v1.x = l1.x + r1.x + b1.x; v1.y = l1.y + r1.y + b1.y;
                    v1.z = l1.z + r1.z + b1.z; v1.w = l1.w + r1.w + b1.w;
                    uint4 h, l; split8(v0, v1, h, l);
                    const uint32_t off = swz(row * 128 + oct * 16);
                    sts128(hiB + off, h.x, h.y, h.z, h.w);
                    sts128(loB + off, l.x, l.y, l.z, l.w);
                }
                fence_proxy_async_s();
                mbar_arrive(sb + SM_FULL(s));
            }
            if (wid < 4 && tl >= 1) {
                const int p = (tl - 1) & 1;
                mbar_wait(sb + SM_EPI(p), epc[p] & 1); epc[p]++;
                fence_after();
                epi_store_chunked(sb, tmem, p, prevTile, arena, wid * 32 + lid);
                fence_before();
                mbar_arrive(sb + SM_EPID(p));
            }
        } else if (mmaLead) {
            const int p = tl & 1;
            if (tp[p] > 0) mbar_wait(sb + SM_EPID(p), (tp[p] - 1) & 1);
            tp[p]++;
            const uint32_t dA = tmem + p * 128;
#pragma unroll
            for (int c = 0; c < 4; c++) {
                const int s = (tl * 4 + c) % NSTAGE;
                mbar_wait(sb + SM_FULL(s), fc[s] & 1); fc[s]++;
                mma_chunk(dA, sb, s, c, c == 0);
                mma_commit(sb + SM_EMPTY(s));
            }
            mma_commit(sb + SM_EPI(p));
        }
        prevTile = tile; tl++;
    }

    if (wid < 4 && tl >= 1) {
        const int p = (tl - 1) & 1;
        mbar_wait(sb + SM_EPI(p), epc[p] & 1); epc[p]++;
        fence_after();
        epi_store_chunked(sb, tmem, p, prevTile, arena, wid * 32 + lid);
        fence_before();
    }
    __syncthreads();
    if (wid == 0) tmem_dealloc(tmem, 256);
#else
    (void)ids; (void)EL; (void)ER; (void)W; (void)bias; (void)numTiles;
#endif
}

// ---------------------------------------------------------------------------
// Persistent tree kernel: 9 levels, 1022 tiles, flag-ordered.
// Issuer: decoupled TMA-issue / MMA-consume cursors over flat chunk stream.
// ---------------------------------------------------------------------------
__global__ __launch_bounds__(NTHREADS, 1)
void tree_tc(const float* __restrict__ W, const float* __restrict__ bias,
             float* __restrict__ out)
{
#if HAS_TCGEN05
    extern __shared__ char dsm[];
    const uint32_t sb = (smem_u32(dsm) + 1023) & ~1023u;
    const int tid = threadIdx.x, wid = tid >> 5, lid = tid & 31;
    const int bid = blockIdx.x;
    char* arena = (char*)g_tree;

    if (tid == 0) {
#pragma unroll
        for (int s = 0; s < NSTAGE; s++) { mbar_init(SM_FULL(s) + sb, 1); mbar_init(SM_EMPTY(s) + sb, 1); }
#pragma unroll
        for (int p = 0; p < 2; p++) { mbar_init(SM_EPI(p) + sb, 1); mbar_init(SM_EPID(p) + sb, 4); }
    }
    if (tid < 128) sts_b32(sb + SM_BIAS + tid * 4, __float_as_uint(bias[tid]));

    {   // B = W chunks
        const int n = tid >> 1, h2 = tid & 1;
#pragma unroll
        for (int g = 0; g < 16; g++) {
            int k0 = h2 * 128 + g * 8;
            float4 v0 = *(const float4*)(W + (size_t)n * KDIM + k0);
            float4 v1 = *(const float4*)(W + (size_t)n * KDIM + k0 + 4);
            uint4 h, l; split8(v0, v1, h, l);
            uint32_t off = (k0 >> 6) * 16384 + swz(n * 128 + (k0 & 63) * 2);
            sts128(sb + SM_B + off, h.x, h.y, h.z, h.w);
            sts128(sb + SM_BLO + off, l.x, l.y, l.z, l.w);
        }
    }
    fence_proxy_async_s();
    __syncthreads();
    if (wid == 0) { tmem_alloc(sb + SM_TMEMP, 256); tmem_relinquish(); }
    __syncthreads();
    const uint32_t tmem = (uint32_t)lds_s32(sb + SM_TMEMP);

    // number of tiles this CTA owns: g = bid + n*148 < NTREE
    const int nMy = (bid < NTREE % 148 || NTREE % 148 == 0)
                    ? (NTREE + 147 - bid) / 148 : NTREE / 148;

    if (wid == 7 && elect_one()) {
        // ---------------- issuer: decoupled cursors ----------------
        const int total = nMy * 4;
        int kIss = 0;
        int issued[NSTAGE] = {0, 0, 0}, fc[NSTAGE] = {0, 0, 0}, tp[2] = {0, 0};

        for (int kCon = 0; kCon < total; kCon++) {
            // top up TMA issues (lookahead < NSTAGE)
            while (kIss < total && kIss < kCon + NSTAGE) {
                const int n = kIss >> 2, c = kIss & 3;
                const int g = bid + n * 148;
                if (c == 0) {
                    int L = 0;
                    while (g >= c_off[L + 1]) L++;
                    if (L > 0) {
                        int* f0 = &g_flags[c_off[L - 1] + 2 * (g - c_off[L])];
                        if (kIss == kCon) {
                            while (ld_acq(f0) < 128 || ld_acq(f0 + 1) < 128) nsleep();
                        } else if (ld_acq(f0) < 128 || ld_acq(f0 + 1) < 128) {
                            break;   // keep consuming; retry later
                        }
                    }
                }
                const int s = kIss % NSTAGE;
                if (issued[s] > 0) mbar_wait(sb + SM_EMPTY(s), (issued[s] - 1) & 1);
                issued[s]++;
                mbar_expect_tx(sb + SM_FULL(s), 32768);
                const char* src = arena + (size_t)g * BLKB + (size_t)c * CHB;
                bulk_g2s(sb + SM_A + s * 32768,         src,         16384, sb + SM_FULL(s));
                bulk_g2s(sb + SM_A + s * 32768 + 16384, src + 16384, 16384, sb + SM_FULL(s));
                kIss++;
            }
            // consume chunk kCon
            const int n = kCon >> 2, c = kCon & 3;
            const int p = n & 1;
            if (c == 0) { if (tp[p] > 0) mbar_wait(sb + SM_EPID(p), (tp[p] - 1) & 1); tp[p]++; }
            const int s = kCon % NSTAGE;
            mbar_wait(sb + SM_FULL(s), fc[s] & 1); fc[s]++;
            mma_chunk(tmem + p * 128, sb, s, c, c == 0);
            mma_commit(sb + SM_EMPTY(s));
            if (c == 3) mma_commit(sb + SM_EPI(p));
        }
    } else if (wid < 4) {
        // ---------------- epilogue warps ----------------
        int epc[2] = {0, 0};
        const int q = wid * 32 + lid;
        for (int n = 0; n < nMy; n++) {
            const int g = bid + n * 148;
            int L = 0;
            while (g >= c_off[L + 1]) L++;
            const int t = g - c_off[L];
            const int p = n & 1;
            mbar_wait(sb + SM_EPI(p), epc[p] & 1); epc[p]++;
            fence_after();
            if (L == 8) {
                float* op = out + (size_t)(128 * t + q) * DDIM;
#pragma unroll
                for (int qq = 0; qq < 4; qq++) {
                    uint32_t d[32];
                    ldtm32(d, tmem + p * 128 + qq * 32);
                    wait_ld();
#pragma unroll
                    for (int u = 0; u < 8; u++) {
                        float4 bv = lds_f32x4(sb + SM_BIAS + (qq * 32 + u * 4) * 4);
                        *(float4*)(op + qq * 32 + u * 4) =
                            make_float4(__uint_as_float(d[4*u+0]) + bv.x, __uint_as_float(d[4*u+1]) + bv.y,
                                        __uint_as_float(d[4*u+2]) + bv.z, __uint_as_float(d[4*u+3]) + bv.w);
                    }
                }
            } else {
                epi_store_chunked(sb, tmem, p, t, arena + (size_t)c_off[L + 1] * BLKB, q);
                red_rel_add1(&g_flags[c_off[L] + t]);   // 128 release arrivals
            }
            fence_before();
            __syncwarp();
            if (lid == 0) mbar_arrive(sb + SM_EPID(p));
        }
    }
    __syncthreads();
    if (wid == 0) tmem_dealloc(tmem, 256);
#else
    (void)W; (void)bias; (void)out;
#endif
}

// ---------------------------------------------------------------------------
extern "C" void kernel_launch(void* const* d_in, const int* in_sizes, int n_in,
                              void* d_out, int out_size)
{
    (void)in_sizes; (void)n_in; (void)out_size;
    const int*   ids  = (const int*)d_in[0];
    const float* emb  = (const float*)d_in[1];
    const float* W    = (const float*)d_in[2];
    const float* bias = (const float*)d_in[3];
    float* out = (float*)d_out;

    static bool attr_set = false;
    if (!attr_set) {
        cudaFuncSetAttribute(precompute_tc, cudaFuncAttributeMaxDynamicSharedMemorySize, DYN_SMEM);
        cudaFuncSetAttribute(fused12_tc,    cudaFuncAttributeMaxDynamicSharedMemorySize, DYN_SMEM);
        cudaFuncSetAttribute(tree_tc,       cudaFuncAttributeMaxDynamicSharedMemorySize, DYN_SMEM);
        attr_set = true;
    }

    float *elp, *erp;
    cudaGetSymbolAddress((void**)&elp, g_EL);
    cudaGetSymbolAddress((void**)&erp, g_ER);

    clear_flags_k<<<4, 256>>>();
    precompute_tc<<<148, NTHREADS, DYN_SMEM>>>(emb, W, elp, erp, VOCABPAD / TILE_M);
    fused12_tc<<<148, NTHREADS, DYN_SMEM>>>(ids, elp, erp, W, bias, 1024);
    tree_tc<<<148, NTHREADS, DYN_SMEM>>>(W, bias, out);
}